// round 1
// baseline (speedup 1.0000x reference)
#include <cuda_runtime.h>
#include <math.h>

// Problem constants (fixed shapes)
#define TT  4096      // tokens = 2*2048
#define HH  1024      // embed
#define FF  2048      // ffn
#define NE  8         // experts
#define GHD 1024      // gate hidden
#define TOPK 2

// ---------------- scratch (device globals; no allocation allowed) -----------
__device__ float g_act[(size_t)TT * GHD];      // gate hidden activations (16MB)
__device__ float g_h[(size_t)2 * TT * FF];     // gathered expert hidden, compact (64MB)
__device__ int   g_idx[NE * TT];               // token id per (expert, slot)
__device__ float g_wt [NE * TT];               // combine weight per (expert, slot)
__device__ int   g_cnt[NE];
__device__ int   g_off[NE];

// ---------------- reset: zero out[] accumulator + counters ------------------
__global__ void k_reset(float* __restrict__ out, int n) {
    int i = blockIdx.x * blockDim.x + threadIdx.x;
    if (i < n) out[i] = 0.0f;
    if (i < NE) g_cnt[i] = 0;
}

// ---------------- gate1: g_act = elu(X @ W + b) ------------------------------
// X [TT,HH], W [HH,GHD], tile 64x64x16, 256 thr, 4x4 per thread
__global__ void k_gate1(const float* __restrict__ X, const float* __restrict__ W,
                        const float* __restrict__ b) {
    __shared__ float As[16][65];
    __shared__ float Bs[16][64];
    int tid = threadIdx.x;
    int tx = tid & 15, ty = tid >> 4;
    int m0 = blockIdx.y * 64, n0 = blockIdx.x * 64;
    int arow = tid >> 2, akq = tid & 3;
    int brow = tid >> 4, bnq = tid & 15;
    float acc[4][4] = {};
    for (int k0 = 0; k0 < HH; k0 += 16) {
        float4 av = *reinterpret_cast<const float4*>(X + (size_t)(m0 + arow) * HH + k0 + akq * 4);
        As[akq*4+0][arow] = av.x; As[akq*4+1][arow] = av.y;
        As[akq*4+2][arow] = av.z; As[akq*4+3][arow] = av.w;
        *reinterpret_cast<float4*>(&Bs[brow][bnq*4]) =
            *reinterpret_cast<const float4*>(W + (size_t)(k0 + brow) * GHD + n0 + bnq * 4);
        __syncthreads();
#pragma unroll
        for (int k = 0; k < 16; k++) {
            float a[4];
#pragma unroll
            for (int i = 0; i < 4; i++) a[i] = As[k][ty*4 + i];
            float4 bv = *reinterpret_cast<const float4*>(&Bs[k][tx*4]);
            float bb[4] = {bv.x, bv.y, bv.z, bv.w};
#pragma unroll
            for (int i = 0; i < 4; i++)
#pragma unroll
                for (int j = 0; j < 4; j++)
                    acc[i][j] = fmaf(a[i], bb[j], acc[i][j]);
        }
        __syncthreads();
    }
#pragma unroll
    for (int i = 0; i < 4; i++) {
        int m = m0 + ty*4 + i;
#pragma unroll
        for (int j = 0; j < 4; j++) {
            int n = n0 + tx*4 + j;
            float v = acc[i][j] + b[n];
            v = (v > 0.0f) ? v : expm1f(v);      // ELU (alpha=1)
            g_act[(size_t)m * GHD + n] = v;
        }
    }
}

// ---------------- routing: logits, softmax, top-2, list append ---------------
// one warp per token
__global__ void k_route(const float* __restrict__ W2, const float* __restrict__ b2,
                        float* __restrict__ logits_out) {
    int gt   = blockIdx.x * (blockDim.x >> 5) + (threadIdx.x >> 5);
    int lane = threadIdx.x & 31;
    if (gt >= TT) return;
    const float* g = g_act + (size_t)gt * GHD;
    float s[NE] = {};
    for (int k = lane; k < GHD; k += 32) {
        float gv = g[k];
        const float* wr = W2 + (size_t)k * NE;
#pragma unroll
        for (int e = 0; e < NE; e++) s[e] = fmaf(gv, wr[e], s[e]);
    }
#pragma unroll
    for (int o = 16; o; o >>= 1)
#pragma unroll
        for (int e = 0; e < NE; e++) s[e] += __shfl_down_sync(0xffffffffu, s[e], o);
    if (lane == 0) {
        float lg[NE];
        float mx = -1e30f;
#pragma unroll
        for (int e = 0; e < NE; e++) {
            lg[e] = s[e] + b2[e];
            logits_out[(size_t)gt * NE + e] = lg[e];
            mx = fmaxf(mx, lg[e]);
        }
        float ex[NE], S = 0.0f;
#pragma unroll
        for (int e = 0; e < NE; e++) { ex[e] = expf(lg[e] - mx); S += ex[e]; }
        float p[NE];
#pragma unroll
        for (int e = 0; e < NE; e++) p[e] = ex[e] / S;
        // top-2, first-occurrence ties (matches jax.lax.top_k)
        int i0 = 0;
#pragma unroll
        for (int e = 1; e < NE; e++) if (p[e] > p[i0]) i0 = e;
        int i1 = -1;
#pragma unroll
        for (int e = 0; e < NE; e++) {
            if (e == i0) continue;
            if (i1 < 0 || p[e] > p[i1]) i1 = e;
        }
        float tw = p[i0] + p[i1];
        float w0 = p[i0] / tw, w1 = p[i1] / tw;
        int q0 = atomicAdd(&g_cnt[i0], 1);
        g_idx[i0 * TT + q0] = gt;  g_wt[i0 * TT + q0] = w0;
        int q1 = atomicAdd(&g_cnt[i1], 1);
        g_idx[i1 * TT + q1] = gt;  g_wt[i1 * TT + q1] = w1;
    }
}

// ---------------- offsets: tiny prefix sum -----------------------------------
__global__ void k_off() {
    if (threadIdx.x == 0) {
        int a = 0;
#pragma unroll
        for (int e = 0; e < NE; e++) { g_off[e] = a; a += g_cnt[e]; }
    }
}

// ---------------- up: h = relu(Xg @ w1_e) * (Xg @ w3_e), gathered ------------
__global__ void k_up(const float* __restrict__ X, const float* __restrict__ W1,
                     const float* __restrict__ W3) {
    int e   = blockIdx.z;
    int cnt = g_cnt[e];
    int m0  = blockIdx.y * 64;
    if (m0 >= cnt) return;
    int n0  = blockIdx.x * 64;
    const float* w1 = W1 + (size_t)e * HH * FF;
    const float* w3 = W3 + (size_t)e * HH * FF;
    __shared__ float As[16][65];
    __shared__ float B1[16][64];
    __shared__ float B3[16][64];
    __shared__ int rows[64];
    int tid = threadIdx.x;
    if (tid < 64) {
        int r = m0 + tid;
        rows[tid] = (r < cnt) ? g_idx[e * TT + r] : -1;
    }
    __syncthreads();
    int tx = tid & 15, ty = tid >> 4;
    int arow = tid >> 2, akq = tid & 3;
    int brow = tid >> 4, bnq = tid & 15;
    int at = rows[arow];
    float acc1[4][4] = {}, acc3[4][4] = {};
    for (int k0 = 0; k0 < HH; k0 += 16) {
        float4 av = make_float4(0.f, 0.f, 0.f, 0.f);
        if (at >= 0)
            av = *reinterpret_cast<const float4*>(X + (size_t)at * HH + k0 + akq * 4);
        As[akq*4+0][arow] = av.x; As[akq*4+1][arow] = av.y;
        As[akq*4+2][arow] = av.z; As[akq*4+3][arow] = av.w;
        *reinterpret_cast<float4*>(&B1[brow][bnq*4]) =
            *reinterpret_cast<const float4*>(w1 + (size_t)(k0 + brow) * FF + n0 + bnq * 4);
        *reinterpret_cast<float4*>(&B3[brow][bnq*4]) =
            *reinterpret_cast<const float4*>(w3 + (size_t)(k0 + brow) * FF + n0 + bnq * 4);
        __syncthreads();
#pragma unroll
        for (int k = 0; k < 16; k++) {
            float a[4];
#pragma unroll
            for (int i = 0; i < 4; i++) a[i] = As[k][ty*4 + i];
            float4 b1v = *reinterpret_cast<const float4*>(&B1[k][tx*4]);
            float4 b3v = *reinterpret_cast<const float4*>(&B3[k][tx*4]);
            float b1a[4] = {b1v.x, b1v.y, b1v.z, b1v.w};
            float b3a[4] = {b3v.x, b3v.y, b3v.z, b3v.w};
#pragma unroll
            for (int i = 0; i < 4; i++)
#pragma unroll
                for (int j = 0; j < 4; j++) {
                    acc1[i][j] = fmaf(a[i], b1a[j], acc1[i][j]);
                    acc3[i][j] = fmaf(a[i], b3a[j], acc3[i][j]);
                }
        }
        __syncthreads();
    }
    int base = g_off[e] + m0;
#pragma unroll
    for (int i = 0; i < 4; i++) {
        int r = ty*4 + i;
        if (m0 + r < cnt) {
            float4 hv;
            hv.x = fmaxf(acc1[i][0], 0.f) * acc3[i][0];
            hv.y = fmaxf(acc1[i][1], 0.f) * acc3[i][1];
            hv.z = fmaxf(acc1[i][2], 0.f) * acc3[i][2];
            hv.w = fmaxf(acc1[i][3], 0.f) * acc3[i][3];
            *reinterpret_cast<float4*>(&g_h[(size_t)(base + r) * FF + n0 + tx*4]) = hv;
        }
    }
}

// ---------------- down: out[t] += w * (h_row @ w2_e) -------------------------
__global__ void k_down(const float* __restrict__ W2, float* __restrict__ out) {
    int e   = blockIdx.z;
    int cnt = g_cnt[e];
    int m0  = blockIdx.y * 64;
    if (m0 >= cnt) return;
    int n0  = blockIdx.x * 64;
    const float* w2 = W2 + (size_t)e * FF * HH;
    __shared__ float As[16][65];
    __shared__ float Bs[16][64];
    int tid = threadIdx.x;
    int tx = tid & 15, ty = tid >> 4;
    int arow = tid >> 2, akq = tid & 3;
    int brow = tid >> 4, bnq = tid & 15;
    int off = g_off[e];
    bool avalid = (m0 + arow) < cnt;
    const float* aptr = g_h + (size_t)(off + m0 + arow) * FF;
    float acc[4][4] = {};
    for (int k0 = 0; k0 < FF; k0 += 16) {
        float4 av = make_float4(0.f, 0.f, 0.f, 0.f);
        if (avalid)
            av = *reinterpret_cast<const float4*>(aptr + k0 + akq * 4);
        As[akq*4+0][arow] = av.x; As[akq*4+1][arow] = av.y;
        As[akq*4+2][arow] = av.z; As[akq*4+3][arow] = av.w;
        *reinterpret_cast<float4*>(&Bs[brow][bnq*4]) =
            *reinterpret_cast<const float4*>(w2 + (size_t)(k0 + brow) * HH + n0 + bnq * 4);
        __syncthreads();
#pragma unroll
        for (int k = 0; k < 16; k++) {
            float a[4];
#pragma unroll
            for (int i = 0; i < 4; i++) a[i] = As[k][ty*4 + i];
            float4 bv = *reinterpret_cast<const float4*>(&Bs[k][tx*4]);
            float bb[4] = {bv.x, bv.y, bv.z, bv.w};
#pragma unroll
            for (int i = 0; i < 4; i++)
#pragma unroll
                for (int j = 0; j < 4; j++)
                    acc[i][j] = fmaf(a[i], bb[j], acc[i][j]);
        }
        __syncthreads();
    }
#pragma unroll
    for (int i = 0; i < 4; i++) {
        int r = ty*4 + i;
        if (m0 + r < cnt) {
            int   t = g_idx[e * TT + m0 + r];
            float w = g_wt [e * TT + m0 + r];
            float* orow = out + (size_t)t * HH + n0 + tx*4;
#pragma unroll
            for (int j = 0; j < 4; j++)
                atomicAdd(&orow[j], w * acc[i][j]);  // exactly 2 adds per element: deterministic
        }
    }
}

// ---------------- launch -----------------------------------------------------
extern "C" void kernel_launch(void* const* d_in, const int* in_sizes, int n_in,
                              void* d_out, int out_size) {
    const float* x   = (const float*)d_in[0];
    const float* gw1 = (const float*)d_in[1];
    const float* gb1 = (const float*)d_in[2];
    const float* gw2 = (const float*)d_in[3];
    const float* gb2 = (const float*)d_in[4];
    const float* w1  = (const float*)d_in[5];
    const float* w3  = (const float*)d_in[6];
    const float* w2  = (const float*)d_in[7];
    float* out    = (float*)d_out;
    float* logits = out + (size_t)TT * HH;   // outputs: [out(T,H) | router_logits(T,E)]

    int nz = TT * HH;
    k_reset<<<(nz + 255) / 256, 256>>>(out, nz);
    k_gate1<<<dim3(GHD / 64, TT / 64), 256>>>(x, gw1, gb1);
    k_route<<<TT / 8, 256>>>(gw2, gb2, logits);
    k_off<<<1, 32>>>();
    k_up  <<<dim3(FF / 64, TT / 64, NE), 256>>>(x, w1, w3);
    k_down<<<dim3(HH / 64, TT / 64, NE), 256>>>(w2, out);
}

// round 4
// speedup vs baseline: 2.0942x; 2.0942x over previous
#include <cuda_runtime.h>
#include <cuda_bf16.h>
#include <math.h>
#include <cstdint>

// Problem constants
#define TT   4096
#define HH   1024
#define FF   2048
#define NE   8
#define GHD  1024
#define K2G  3072      // 3*HH  (split-K'' for gate/up GEMMs)
#define K2D  6144      // 3*FF  (split-K'' for down GEMM)
#define CROWS 8192     // total compact expert rows = 2*TT (always exact: top-2)

// ------------------------- device scratch (no allocs allowed) ---------------
__device__ __nv_bfloat16 g_xs  [(size_t)TT * K2G];        // X split   [T, 3H]  zones [Ah,Ah,Al]
__device__ __nv_bfloat16 g_gw1s[(size_t)GHD * K2G];       // gw1^T split [N,3K] zones [Bh,Bl,Bh]
__device__ __nv_bfloat16 g_w1s [(size_t)NE * FF * K2G];
__device__ __nv_bfloat16 g_w3s [(size_t)NE * FF * K2G];
__device__ __nv_bfloat16 g_w2s [(size_t)NE * HH * K2D];
__device__ __nv_bfloat16 g_hs  [(size_t)CROWS * K2D];     // expert hidden split [rows, 3F] zones [Ah,Ah,Al]
__device__ float g_t1 [(size_t)CROWS * FF];               // x@w1 (compact rows)
__device__ float g_t3 [(size_t)CROWS * FF];               // x@w3
__device__ float g_act[(size_t)TT * GHD];                 // gate hidden (fp32, for routing)
__device__ int   g_idx[NE * TT];
__device__ float g_wt [NE * TT];
__device__ int   g_cnt[NE];
__device__ int   g_off[NE];

// ------------------------- PTX helpers --------------------------------------
__device__ __forceinline__ uint32_t smem_u32(const void* p) {
    uint32_t a;
    asm("{ .reg .u64 t; cvta.to.shared.u64 t, %1; cvt.u32.u64 %0, t; }" : "=r"(a) : "l"(p));
    return a;
}
#define CP16(dst, src) \
    asm volatile("cp.async.cg.shared.global [%0], [%1], 16;" :: "r"(dst), "l"(src))
#define CP_COMMIT() asm volatile("cp.async.commit_group;" ::: "memory")
#define CP_WAIT(n)  asm volatile("cp.async.wait_group %0;" :: "n"(n) : "memory")

#define LDSM4(r0, r1, r2, r3, addr) \
    asm volatile("ldmatrix.sync.aligned.m8n8.x4.shared.b16 {%0,%1,%2,%3}, [%4];" \
        : "=r"(r0), "=r"(r1), "=r"(r2), "=r"(r3) : "r"(addr))

#define MMA16816(d, a, b) \
    asm volatile("mma.sync.aligned.m16n8k16.row.col.f32.bf16.bf16.f32 " \
        "{%0,%1,%2,%3}, {%4,%5,%6,%7}, {%8,%9}, {%0,%1,%2,%3};" \
        : "+f"((d)[0]), "+f"((d)[1]), "+f"((d)[2]), "+f"((d)[3]) \
        : "r"((a)[0]), "r"((a)[1]), "r"((a)[2]), "r"((a)[3]), "r"((b)[0]), "r"((b)[1]))

__device__ __forceinline__ void bsplit(float v, __nv_bfloat16& h, __nv_bfloat16& l) {
    h = __float2bfloat16_rn(v);
    l = __float2bfloat16_rn(v - __bfloat162float(h));
}

// ------------------------- small kernels ------------------------------------
__global__ void k_reset(float* __restrict__ out, int n) {
    int i = blockIdx.x * blockDim.x + threadIdx.x;
    if (i < n) out[i] = 0.0f;
    if (i < NE) g_cnt[i] = 0;
}

// X [T,H] fp32 -> g_xs [T,3H] bf16 zones [hi, hi, lo]
__global__ void k_splitX(const float* __restrict__ X) {
    int i = blockIdx.x * blockDim.x + threadIdx.x;   // over T*H
    if (i >= TT * HH) return;
    int t = i >> 10, k = i & 1023;
    __nv_bfloat16 h, l; bsplit(X[i], h, l);
    __nv_bfloat16* r = g_xs + (size_t)t * K2G;
    r[k] = h; r[HH + k] = h; r[2 * HH + k] = l;
}

// in [R,C] fp32 (per expert slab z) -> out [C,3R] bf16 zones [hi, lo, hi]
__global__ void k_trsplit(const float* __restrict__ in, __nv_bfloat16* __restrict__ out,
                          int R, int C) {
    __shared__ float t[32][33];
    size_t ioff = (size_t)blockIdx.z * R * C;
    size_t ooff = (size_t)blockIdx.z * C * 3 * R;
    int c0 = blockIdx.x * 32, r0 = blockIdx.y * 32;
#pragma unroll
    for (int i = threadIdx.y; i < 32; i += 8)
        t[i][threadIdx.x] = in[ioff + (size_t)(r0 + i) * C + c0 + threadIdx.x];
    __syncthreads();
#pragma unroll
    for (int i = threadIdx.y; i < 32; i += 8) {
        float v = t[threadIdx.x][i];              // = in[r0+tx][c0+i]
        __nv_bfloat16 h, l; bsplit(v, h, l);
        __nv_bfloat16* orow = out + ooff + (size_t)(c0 + i) * 3 * R;
        int k = r0 + threadIdx.x;
        orow[k] = h; orow[R + k] = l; orow[2 * R + k] = h;
    }
}

// h = relu(t1)*t3 -> g_hs [rows,3F] zones [hi, hi, lo]
__global__ void k_hsplit() {
    int i = blockIdx.x * blockDim.x + threadIdx.x;   // over CROWS*FF
    if (i >= CROWS * FF) return;
    int r = i >> 11, k = i & 2047;
    float v = fmaxf(g_t1[i], 0.0f) * g_t3[i];
    __nv_bfloat16 h, l; bsplit(v, h, l);
    __nv_bfloat16* row = g_hs + (size_t)r * K2D;
    row[k] = h; row[FF + k] = h; row[2 * FF + k] = l;
}

// routing: one warp per token (reads fp32 g_act)
__global__ void k_route(const float* __restrict__ W2, const float* __restrict__ b2,
                        float* __restrict__ logits_out) {
    int gt = blockIdx.x * (blockDim.x >> 5) + (threadIdx.x >> 5);
    int lane = threadIdx.x & 31;
    if (gt >= TT) return;
    const float* g = g_act + (size_t)gt * GHD;
    float s[NE] = {};
    for (int k = lane; k < GHD; k += 32) {
        float gv = g[k];
        const float* wr = W2 + (size_t)k * NE;
#pragma unroll
        for (int e = 0; e < NE; e++) s[e] = fmaf(gv, wr[e], s[e]);
    }
#pragma unroll
    for (int o = 16; o; o >>= 1)
#pragma unroll
        for (int e = 0; e < NE; e++) s[e] += __shfl_down_sync(0xffffffffu, s[e], o);
    if (lane == 0) {
        float lg[NE]; float mx = -1e30f;
#pragma unroll
        for (int e = 0; e < NE; e++) {
            lg[e] = s[e] + b2[e];
            logits_out[(size_t)gt * NE + e] = lg[e];
            mx = fmaxf(mx, lg[e]);
        }
        float ex[NE], S = 0.0f;
#pragma unroll
        for (int e = 0; e < NE; e++) { ex[e] = expf(lg[e] - mx); S += ex[e]; }
        float p[NE];
#pragma unroll
        for (int e = 0; e < NE; e++) p[e] = ex[e] / S;
        int i0 = 0;
#pragma unroll
        for (int e = 1; e < NE; e++) if (p[e] > p[i0]) i0 = e;
        int i1 = -1;
#pragma unroll
        for (int e = 0; e < NE; e++) {
            if (e == i0) continue;
            if (i1 < 0 || p[e] > p[i1]) i1 = e;
        }
        float tw = p[i0] + p[i1];
        int q0 = atomicAdd(&g_cnt[i0], 1);
        g_idx[i0 * TT + q0] = gt;  g_wt[i0 * TT + q0] = p[i0] / tw;
        int q1 = atomicAdd(&g_cnt[i1], 1);
        g_idx[i1 * TT + q1] = gt;  g_wt[i1 * TT + q1] = p[i1] / tw;
    }
}

__global__ void k_off_k() {
    if (threadIdx.x == 0) {
        int a = 0;
#pragma unroll
        for (int e = 0; e < NE; e++) { g_off[e] = a; a += g_cnt[e]; }
    }
}

// ------------------------- generic bf16 mma.sync GEMM ------------------------
// C[M,N] = A''[M,K2] @ B''[N,K2]^T, fp32 accum. Tile 128x128x32, 256 thr,
// 4-stage cp.async, ldmatrix, mma.m16n8k16.
// MODE 0: gate  (A=g_xs direct, out=g_act with bias+ELU, N=GHD)
// MODE 1: up    (A=g_xs gathered via g_idx[e], out=fp32 temp at compact rows, N=FF)
// MODE 2: down  (A=g_hs at compact rows, out += w * C scattered to tokens, N=HH)
template <int MODE>
__global__ void __launch_bounds__(256)
k_gemm(const __nv_bfloat16* __restrict__ Ab, const __nv_bfloat16* __restrict__ Bb,
       int K2, float* __restrict__ outp, const float* __restrict__ bias) {
    const int e = blockIdx.z;
    const int m0 = blockIdx.y * 128, n0 = blockIdx.x * 128;
    int cnt, hoff = 0;
    if (MODE == 0) cnt = TT;
    else {
        cnt = g_cnt[e];
        if (m0 >= cnt) return;
        if (MODE == 2) hoff = g_off[e];
    }
    const int bRows = (MODE == 1) ? FF : ((MODE == 2) ? HH : GHD);
    const __nv_bfloat16* Bex = Bb + (MODE == 0 ? (size_t)0 : (size_t)e * bRows * K2);

    extern __shared__ char sm[];
    const uint32_t sbase = smem_u32(sm);
    const int tid = threadIdx.x;
    const int lane = tid & 31, wid = tid >> 5;
    const int wm = wid & 1, wn = wid >> 1;     // warp tile: 64(M) x 32(N)

    // ---- per-thread gmem load rows (fixed): A row = tid>>1, B row = tid>>1
    const int lr = tid >> 1, cp = tid & 1;
    const __nv_bfloat16* arow;
    if (MODE == 0) {
        arow = Ab + (size_t)(m0 + lr) * K2;
    } else if (MODE == 1) {
        int slot = m0 + lr; if (slot >= cnt) slot = cnt - 1;
        arow = Ab + (size_t)g_idx[e * TT + slot] * K2;
    } else {
        int rr = hoff + m0 + lr; if (rr > CROWS - 1) rr = CROWS - 1;
        arow = Ab + (size_t)rr * K2;
    }
    const __nv_bfloat16* brow = Bex + (size_t)(n0 + lr) * K2;
    // smem dst offsets (stage-relative), swizzle chunk' = chunk ^ ((row>>1)&3)
    const int sel = (lr >> 1) & 3;
    const uint32_t dA0 = lr * 64 + (((cp * 2 + 0) ^ sel) << 4);
    const uint32_t dA1 = lr * 64 + (((cp * 2 + 1) ^ sel) << 4);

    // ---- ldmatrix lane address components
    const int t8 = lane >> 3, i7 = lane & 7;
    const int rowA = wm * 64 + (t8 & 1) * 8 + i7;   // + f*16
    const int rowB = wn * 32 + (t8 >> 1) * 8 + i7;  // + p*16
    const int selA = (rowA >> 1) & 3, cbA = t8 >> 1;
    const int selB = (rowB >> 1) & 3, cbB = t8 & 1;

    float acc[4][4][4] = {};

    const int KT = K2 >> 5;
    // prologue: fill stages 0..2
#pragma unroll
    for (int s = 0; s < 3; s++) {
        uint32_t st = sbase + s * 16384;
        const __nv_bfloat16* as = arow + s * 32 + cp * 16;
        const __nv_bfloat16* bs = brow + s * 32 + cp * 16;
        CP16(st + dA0, as);
        CP16(st + dA1, as + 8);
        CP16(st + 8192 + dA0, bs);
        CP16(st + 8192 + dA1, bs + 8);
        CP_COMMIT();
    }

    for (int kt = 0; kt < KT; kt++) {
        CP_WAIT(2);
        __syncthreads();
        uint32_t stA = sbase + (kt & 3) * 16384;
        uint32_t stB = stA + 8192;
#pragma unroll
        for (int ks = 0; ks < 2; ks++) {
            uint32_t A[4][4], Bf[4][2];
#pragma unroll
            for (int f = 0; f < 4; f++) {
                uint32_t ad = stA + (rowA + f * 16) * 64 + (((ks * 2 + cbA) ^ selA) << 4);
                LDSM4(A[f][0], A[f][1], A[f][2], A[f][3], ad);
            }
#pragma unroll
            for (int p = 0; p < 2; p++) {
                uint32_t bd = stB + (rowB + p * 16) * 64 + (((ks * 2 + cbB) ^ selB) << 4);
                LDSM4(Bf[2 * p][0], Bf[2 * p][1], Bf[2 * p + 1][0], Bf[2 * p + 1][1], bd);
            }
#pragma unroll
            for (int f = 0; f < 4; f++)
#pragma unroll
                for (int g = 0; g < 4; g++)
                    MMA16816(acc[f][g], A[f], Bf[g]);
        }
        int nk = kt + 3;
        if (nk < KT) {
            uint32_t st = sbase + (nk & 3) * 16384;
            const __nv_bfloat16* as = arow + nk * 32 + cp * 16;
            const __nv_bfloat16* bs = brow + nk * 32 + cp * 16;
            CP16(st + dA0, as);
            CP16(st + dA1, as + 8);
            CP16(st + 8192 + dA0, bs);
            CP16(st + 8192 + dA1, bs + 8);
        }
        CP_COMMIT();
    }

    // ---- epilogue
    const int rg = lane >> 2, cq = (lane & 3) * 2;
#pragma unroll
    for (int f = 0; f < 4; f++) {
#pragma unroll
        for (int half = 0; half < 2; half++) {
            int mrel = wm * 64 + f * 16 + rg + half * 8;   // row within CTA tile
#pragma unroll
            for (int g = 0; g < 4; g++) {
                float v0 = acc[f][g][half * 2 + 0];
                float v1 = acc[f][g][half * 2 + 1];
                int n = n0 + wn * 32 + g * 8 + cq;
                if (MODE == 0) {
                    int m = m0 + mrel;
                    float a0 = v0 + bias[n], a1 = v1 + bias[n + 1];
                    a0 = a0 > 0.f ? a0 : expm1f(a0);
                    a1 = a1 > 0.f ? a1 : expm1f(a1);
                    float2* dst = (float2*)&g_act[(size_t)m * GHD + n];
                    *dst = make_float2(a0, a1);
                } else if (MODE == 1) {
                    int slot = m0 + mrel;
                    if (slot < cnt) {
                        size_t ro = (size_t)(g_off[e] + slot) * FF + n;
                        *(float2*)&outp[ro] = make_float2(v0, v1);
                    }
                } else {
                    int slot = m0 + mrel;
                    if (slot < cnt) {
                        int tok = g_idx[e * TT + slot];
                        float w = g_wt[e * TT + slot];
                        float* orow = outp + (size_t)tok * HH + n;
                        atomicAdd(&orow[0], w * v0);
                        atomicAdd(&orow[1], w * v1);
                    }
                }
            }
        }
    }
}

// ------------------------- launch -------------------------------------------
extern "C" void kernel_launch(void* const* d_in, const int* in_sizes, int n_in,
                              void* d_out, int out_size) {
    const float* x   = (const float*)d_in[0];
    const float* gw1 = (const float*)d_in[1];
    const float* gb1 = (const float*)d_in[2];
    const float* gw2 = (const float*)d_in[3];
    const float* gb2 = (const float*)d_in[4];
    const float* w1  = (const float*)d_in[5];
    const float* w3  = (const float*)d_in[6];
    const float* w2  = (const float*)d_in[7];
    float* out    = (float*)d_out;
    float* logits = out + (size_t)TT * HH;

    __nv_bfloat16 *d_xs, *d_gw1s, *d_w1s, *d_w3s, *d_w2s;
    cudaGetSymbolAddress((void**)&d_xs,   g_xs);
    cudaGetSymbolAddress((void**)&d_gw1s, g_gw1s);
    cudaGetSymbolAddress((void**)&d_w1s,  g_w1s);
    cudaGetSymbolAddress((void**)&d_w3s,  g_w3s);
    cudaGetSymbolAddress((void**)&d_w2s,  g_w2s);
    __nv_bfloat16* d_hs;
    cudaGetSymbolAddress((void**)&d_hs,   g_hs);
    float *d_t1, *d_t3, *d_act;
    cudaGetSymbolAddress((void**)&d_t1, g_t1);
    cudaGetSymbolAddress((void**)&d_t3, g_t3);
    cudaGetSymbolAddress((void**)&d_act, g_act);

    const int SMEM = 4 * 16384;   // 64KB
    cudaFuncSetAttribute(k_gemm<0>, cudaFuncAttributeMaxDynamicSharedMemorySize, SMEM);
    cudaFuncSetAttribute(k_gemm<1>, cudaFuncAttributeMaxDynamicSharedMemorySize, SMEM);
    cudaFuncSetAttribute(k_gemm<2>, cudaFuncAttributeMaxDynamicSharedMemorySize, SMEM);

    int nz = TT * HH;
    k_reset<<<(nz + 255) / 256, 256>>>(out, nz);
    k_splitX<<<(TT * HH + 255) / 256, 256>>>(x);
    k_trsplit<<<dim3(GHD / 32, HH / 32, 1),  dim3(32, 8)>>>(gw1, d_gw1s, HH, GHD);
    k_trsplit<<<dim3(FF / 32,  HH / 32, NE), dim3(32, 8)>>>(w1,  d_w1s,  HH, FF);
    k_trsplit<<<dim3(FF / 32,  HH / 32, NE), dim3(32, 8)>>>(w3,  d_w3s,  HH, FF);
    k_trsplit<<<dim3(HH / 32,  FF / 32, NE), dim3(32, 8)>>>(w2,  d_w2s,  FF, HH);

    // gate: [4096,3072] @ [1024,3072]^T -> g_act (bias+ELU)
    k_gemm<0><<<dim3(GHD / 128, TT / 128, 1), 256, SMEM>>>(d_xs, d_gw1s, K2G, d_act, gb1);
    k_route<<<TT / 8, 256>>>(gw2, gb2, logits);
    k_off_k<<<1, 32>>>();
    // up: gathered [cnt,3072] @ [2048,3072]^T -> t1 / t3
    k_gemm<1><<<dim3(FF / 128, TT / 128, NE), 256, SMEM>>>(d_xs, d_w1s, K2G, d_t1, nullptr);
    k_gemm<1><<<dim3(FF / 128, TT / 128, NE), 256, SMEM>>>(d_xs, d_w3s, K2G, d_t3, nullptr);
    k_hsplit<<<(CROWS * FF + 255) / 256, 256>>>();
    // down: [cnt,6144] @ [1024,6144]^T -> weighted scatter-add into out
    k_gemm<2><<<dim3(HH / 128, TT / 128, NE), 256, SMEM>>>(d_hs, d_w2s, K2D, out, nullptr);
}

// round 6
// speedup vs baseline: 2.3522x; 1.1232x over previous
#include <cuda_runtime.h>
#include <cuda_bf16.h>
#include <math.h>
#include <cstdint>

// Problem constants
#define TT   4096
#define HH   1024
#define FF   2048
#define NE   8
#define GHD  1024
#define K2G  3072      // 3*HH  (split-K'' for gate/up GEMMs)
#define K2D  6144      // 3*FF  (split-K'' for down GEMM)
#define CROWS 8192     // total compact expert rows = 2*TT (top-2 exact)

// ------------------------- device scratch (no allocs allowed) ---------------
__device__ __nv_bfloat16 g_xs  [(size_t)TT * K2G];        // X split   [T,3H]  zones [Ah,Ah,Al]
__device__ __nv_bfloat16 g_gw1s[(size_t)GHD * K2G];       // gw1^T split [N,3K] zones [Bh,Bl,Bh]
__device__ __nv_bfloat16 g_w1s [(size_t)NE * FF * K2G];
__device__ __nv_bfloat16 g_w3s [(size_t)NE * FF * K2G];
__device__ __nv_bfloat16 g_w2s [(size_t)NE * HH * K2D];
__device__ __nv_bfloat16 g_hs  [(size_t)CROWS * K2D];     // expert hidden split [rows,3F] zones [Ah,Ah,Al]
__device__ float g_act[(size_t)TT * GHD];                 // gate hidden (fp32, for routing)
__device__ int   g_idx[NE * TT];
__device__ float g_wt [NE * TT];
__device__ int   g_cnt[NE];
__device__ int   g_off[NE];

// ------------------------- PTX helpers --------------------------------------
__device__ __forceinline__ uint32_t smem_u32(const void* p) {
    uint32_t a;
    asm("{ .reg .u64 t; cvta.to.shared.u64 t, %1; cvt.u32.u64 %0, t; }" : "=r"(a) : "l"(p));
    return a;
}
#define CP16(dst, src) \
    asm volatile("cp.async.cg.shared.global [%0], [%1], 16;" :: "r"(dst), "l"(src))
#define CP_COMMIT() asm volatile("cp.async.commit_group;" ::: "memory")
#define CP_WAIT(n)  asm volatile("cp.async.wait_group %0;" :: "n"(n) : "memory")

#define LDSM4(r0, r1, r2, r3, addr) \
    asm volatile("ldmatrix.sync.aligned.m8n8.x4.shared.b16 {%0,%1,%2,%3}, [%4];" \
        : "=r"(r0), "=r"(r1), "=r"(r2), "=r"(r3) : "r"(addr))

#define MMA16816(d, a, b) \
    asm volatile("mma.sync.aligned.m16n8k16.row.col.f32.bf16.bf16.f32 " \
        "{%0,%1,%2,%3}, {%4,%5,%6,%7}, {%8,%9}, {%0,%1,%2,%3};" \
        : "+f"((d)[0]), "+f"((d)[1]), "+f"((d)[2]), "+f"((d)[3]) \
        : "r"((a)[0]), "r"((a)[1]), "r"((a)[2]), "r"((a)[3]), "r"((b)[0]), "r"((b)[1]))

__device__ __forceinline__ void bsplit(float v, __nv_bfloat16& h, __nv_bfloat16& l) {
    h = __float2bfloat16_rn(v);
    l = __float2bfloat16_rn(v - __bfloat162float(h));
}

// ------------------------- small kernels ------------------------------------
__global__ void k_reset(float* __restrict__ out, int n) {
    int i = blockIdx.x * blockDim.x + threadIdx.x;
    if (i < n) out[i] = 0.0f;
    if (i < NE) g_cnt[i] = 0;
}

// X [T,H] fp32 -> g_xs [T,3H] bf16 zones [hi, hi, lo]
__global__ void k_splitX(const float* __restrict__ X) {
    int i = blockIdx.x * blockDim.x + threadIdx.x;
    if (i >= TT * HH) return;
    int t = i >> 10, k = i & 1023;
    __nv_bfloat16 h, l; bsplit(X[i], h, l);
    __nv_bfloat16* r = g_xs + (size_t)t * K2G;
    r[k] = h; r[HH + k] = h; r[2 * HH + k] = l;
}

// in [R,C] fp32 (slab z) -> out [C,3R] bf16 zones [hi, lo, hi]
// tile 64 rows x 32 cols; stores paired-k as bfloat162 (4B coalesced)
__global__ void k_trsplit(const float* __restrict__ in, __nv_bfloat16* __restrict__ out,
                          int R, int C) {
    __shared__ float t[64][33];
    size_t ioff = (size_t)blockIdx.z * R * C;
    size_t ooff = (size_t)blockIdx.z * C * 3 * R;
    int c0 = blockIdx.x * 32, r0 = blockIdx.y * 64;
    int tx = threadIdx.x, ty = threadIdx.y;
#pragma unroll
    for (int i = ty; i < 64; i += 8)
        t[i][tx] = in[ioff + (size_t)(r0 + i) * C + c0 + tx];
    __syncthreads();
    int tid = ty * 32 + tx;
    int crel = tid >> 5;          // 0..7
    int kp   = tid & 31;          // 0..31 -> k pair
#pragma unroll
    for (int j = 0; j < 4; j++) {
        int cidx = crel + 8 * j;                 // 0..31
        float v0 = t[2 * kp + 0][cidx];
        float v1 = t[2 * kp + 1][cidx];
        __nv_bfloat16 h0, l0, h1, l1;
        bsplit(v0, h0, l0); bsplit(v1, h1, l1);
        __nv_bfloat162 hi; hi.x = h0; hi.y = h1;
        __nv_bfloat162 lo; lo.x = l0; lo.y = l1;
        __nv_bfloat16* orow = out + ooff + (size_t)(c0 + cidx) * 3 * R;
        int k = r0 + 2 * kp;
        *(__nv_bfloat162*)&orow[k]         = hi;
        *(__nv_bfloat162*)&orow[R + k]     = lo;
        *(__nv_bfloat162*)&orow[2 * R + k] = hi;
    }
}

// routing: one warp per token (reads fp32 g_act)
__global__ void k_route(const float* __restrict__ W2, const float* __restrict__ b2,
                        float* __restrict__ logits_out) {
    int gt = blockIdx.x * (blockDim.x >> 5) + (threadIdx.x >> 5);
    int lane = threadIdx.x & 31;
    if (gt >= TT) return;
    const float* g = g_act + (size_t)gt * GHD;
    float s[NE] = {};
    for (int k = lane; k < GHD; k += 32) {
        float gv = g[k];
        const float* wr = W2 + (size_t)k * NE;
#pragma unroll
        for (int e = 0; e < NE; e++) s[e] = fmaf(gv, wr[e], s[e]);
    }
#pragma unroll
    for (int o = 16; o; o >>= 1)
#pragma unroll
        for (int e = 0; e < NE; e++) s[e] += __shfl_down_sync(0xffffffffu, s[e], o);
    if (lane == 0) {
        float lg[NE]; float mx = -1e30f;
#pragma unroll
        for (int e = 0; e < NE; e++) {
            lg[e] = s[e] + b2[e];
            logits_out[(size_t)gt * NE + e] = lg[e];
            mx = fmaxf(mx, lg[e]);
        }
        float ex[NE], S = 0.0f;
#pragma unroll
        for (int e = 0; e < NE; e++) { ex[e] = expf(lg[e] - mx); S += ex[e]; }
        float p[NE];
#pragma unroll
        for (int e = 0; e < NE; e++) p[e] = ex[e] / S;
        int i0 = 0;
#pragma unroll
        for (int e = 1; e < NE; e++) if (p[e] > p[i0]) i0 = e;
        int i1 = -1;
#pragma unroll
        for (int e = 0; e < NE; e++) {
            if (e == i0) continue;
            if (i1 < 0 || p[e] > p[i1]) i1 = e;
        }
        float tw = p[i0] + p[i1];
        int q0 = atomicAdd(&g_cnt[i0], 1);
        g_idx[i0 * TT + q0] = gt;  g_wt[i0 * TT + q0] = p[i0] / tw;
        int q1 = atomicAdd(&g_cnt[i1], 1);
        g_idx[i1 * TT + q1] = gt;  g_wt[i1 * TT + q1] = p[i1] / tw;
    }
}

__global__ void k_off_k() {
    if (threadIdx.x == 0) {
        int a = 0;
#pragma unroll
        for (int e = 0; e < NE; e++) { g_off[e] = a; a += g_cnt[e]; }
    }
}

// ------------------------- generic bf16 mma.sync GEMM (gate / down) ----------
// Tile 128x128x32, 256 thr (warp 64x32), 4-stage cp.async, 2 CTAs/SM.
// MODE 0: gate (out=g_act, bias+ELU). MODE 2: down (out += w*C scatter).
template <int MODE>
__global__ void __launch_bounds__(256, 2)
k_gemm(const __nv_bfloat16* __restrict__ Ab, const __nv_bfloat16* __restrict__ Bb,
       int K2, float* __restrict__ outp, const float* __restrict__ bias) {
    const int e = blockIdx.z;
    const int m0 = blockIdx.y * 128, n0 = blockIdx.x * 128;
    int cnt, hoff = 0;
    if (MODE == 0) cnt = TT;
    else {
        cnt = g_cnt[e];
        if (m0 >= cnt) return;
        hoff = g_off[e];
    }
    const int bRows = (MODE == 2) ? HH : GHD;
    const __nv_bfloat16* Bex = Bb + (MODE == 0 ? (size_t)0 : (size_t)e * bRows * K2);

    extern __shared__ char sm[];
    const uint32_t sbase = smem_u32(sm);
    const int tid = threadIdx.x;
    const int lane = tid & 31, wid = tid >> 5;
    const int wm = wid & 1, wn = wid >> 1;     // warp tile 64(M) x 32(N)

    const int lr = tid >> 1, cp = tid & 1;
    const __nv_bfloat16* arow;
    if (MODE == 0) {
        arow = Ab + (size_t)(m0 + lr) * K2;
    } else {
        int rr = hoff + m0 + lr; if (rr > CROWS - 1) rr = CROWS - 1;
        arow = Ab + (size_t)rr * K2;
    }
    const __nv_bfloat16* brow = Bex + (size_t)(n0 + lr) * K2;
    const int sel = (lr >> 1) & 3;
    const uint32_t dA0 = lr * 64 + (((cp * 2 + 0) ^ sel) << 4);
    const uint32_t dA1 = lr * 64 + (((cp * 2 + 1) ^ sel) << 4);

    const int t8 = lane >> 3, i7 = lane & 7;
    const int rowA = wm * 64 + (t8 & 1) * 8 + i7;
    const int rowB = wn * 32 + (t8 >> 1) * 8 + i7;
    const int selA = (rowA >> 1) & 3, cbA = t8 >> 1;
    const int selB = (rowB >> 1) & 3, cbB = t8 & 1;

    float acc[4][4][4] = {};
    const int KT = K2 >> 5;
#pragma unroll
    for (int s = 0; s < 3; s++) {
        uint32_t st = sbase + s * 16384;
        const __nv_bfloat16* as = arow + s * 32 + cp * 16;
        const __nv_bfloat16* bs = brow + s * 32 + cp * 16;
        CP16(st + dA0, as);
        CP16(st + dA1, as + 8);
        CP16(st + 8192 + dA0, bs);
        CP16(st + 8192 + dA1, bs + 8);
        CP_COMMIT();
    }

    for (int kt = 0; kt < KT; kt++) {
        CP_WAIT(2);
        __syncthreads();
        uint32_t stA = sbase + (kt & 3) * 16384;
        uint32_t stB = stA + 8192;
#pragma unroll
        for (int ks = 0; ks < 2; ks++) {
            uint32_t A[4][4], Bf[4][2];
#pragma unroll
            for (int f = 0; f < 4; f++) {
                uint32_t ad = stA + (rowA + f * 16) * 64 + (((ks * 2 + cbA) ^ selA) << 4);
                LDSM4(A[f][0], A[f][1], A[f][2], A[f][3], ad);
            }
#pragma unroll
            for (int p = 0; p < 2; p++) {
                uint32_t bd = stB + (rowB + p * 16) * 64 + (((ks * 2 + cbB) ^ selB) << 4);
                LDSM4(Bf[2 * p][0], Bf[2 * p][1], Bf[2 * p + 1][0], Bf[2 * p + 1][1], bd);
            }
#pragma unroll
            for (int f = 0; f < 4; f++)
#pragma unroll
                for (int g = 0; g < 4; g++)
                    MMA16816(acc[f][g], A[f], Bf[g]);
        }
        int nk = kt + 3;
        if (nk < KT) {
            uint32_t st = sbase + (nk & 3) * 16384;
            const __nv_bfloat16* as = arow + nk * 32 + cp * 16;
            const __nv_bfloat16* bs = brow + nk * 32 + cp * 16;
            CP16(st + dA0, as);
            CP16(st + dA1, as + 8);
            CP16(st + 8192 + dA0, bs);
            CP16(st + 8192 + dA1, bs + 8);
        }
        CP_COMMIT();
    }

    const int rg = lane >> 2, cq = (lane & 3) * 2;
#pragma unroll
    for (int f = 0; f < 4; f++) {
#pragma unroll
        for (int half = 0; half < 2; half++) {
            int mrel = wm * 64 + f * 16 + rg + half * 8;
#pragma unroll
            for (int g = 0; g < 4; g++) {
                float v0 = acc[f][g][half * 2 + 0];
                float v1 = acc[f][g][half * 2 + 1];
                int n = n0 + wn * 32 + g * 8 + cq;
                if (MODE == 0) {
                    int m = m0 + mrel;
                    float a0 = v0 + bias[n], a1 = v1 + bias[n + 1];
                    a0 = a0 > 0.f ? a0 : expm1f(a0);
                    a1 = a1 > 0.f ? a1 : expm1f(a1);
                    *(float2*)&g_act[(size_t)m * GHD + n] = make_float2(a0, a1);
                } else {
                    int slot = m0 + mrel;
                    if (slot < cnt) {
                        int tok = g_idx[e * TT + slot];
                        float w = g_wt[e * TT + slot];
                        float* orow = outp + (size_t)tok * HH + n;
                        atomicAdd(&orow[0], w * v0);
                        atomicAdd(&orow[1], w * v1);
                    }
                }
            }
        }
    }
}

// ------------------- fused up GEMM: h = relu(Xg@w1)*(Xg@w3) ------------------
// 512 thr, CTA 128(M) x [128(w1)+128(w3)], warp tile 32 x (32+32), 4-stage.
// Epilogue: h + bf16-split directly into g_hs (zones [hi,hi,lo]).
__global__ void __launch_bounds__(512)
k_upfused(const __nv_bfloat16* __restrict__ Ab) {
    const int e = blockIdx.z;
    const int cnt = g_cnt[e];
    const int m0 = blockIdx.y * 128;
    if (m0 >= cnt) return;
    const int n0 = blockIdx.x * 128;

    extern __shared__ char sm[];
    const uint32_t sbase = smem_u32(sm);
    const int tid = threadIdx.x;
    const int lane = tid & 31, wid = tid >> 5;
    const int wm = wid & 3, wn = wid >> 2;     // 4x4 warps, tile 32 x (32+32)

    // loaders: 1 CP16 per thread per buffer (A, B1, B3)
    const int lr = tid >> 2, cp = tid & 3;     // 128 rows x 4 chunks(16B)
    int slot = m0 + lr; if (slot >= cnt) slot = cnt - 1;
    const __nv_bfloat16* arow  = Ab + (size_t)g_idx[e * TT + slot] * K2G;
    const __nv_bfloat16* b1row = g_w1s + (size_t)e * FF * K2G + (size_t)(n0 + lr) * K2G;
    const __nv_bfloat16* b3row = g_w3s + (size_t)e * FF * K2G + (size_t)(n0 + lr) * K2G;
    const int sel = (lr >> 1) & 3;
    const uint32_t dOff = lr * 64 + ((cp ^ sel) << 4);

    const int t8 = lane >> 3, i7 = lane & 7;
    const int rowA = wm * 32 + (t8 & 1) * 8 + i7;
    const int rowB = wn * 32 + (t8 >> 1) * 8 + i7;
    const int selA = (rowA >> 1) & 3, cbA = t8 >> 1;
    const int selB = (rowB >> 1) & 3, cbB = t8 & 1;

    float acc1[2][4][4] = {}, acc3[2][4][4] = {};
    const int KT = K2G >> 5;   // 96
#pragma unroll
    for (int s = 0; s < 3; s++) {
        uint32_t st = sbase + s * 24576;
        int col = s * 32 + cp * 8;
        CP16(st +         dOff, arow  + col);
        CP16(st +  8192 + dOff, b1row + col);
        CP16(st + 16384 + dOff, b3row + col);
        CP_COMMIT();
    }

    for (int kt = 0; kt < KT; kt++) {
        CP_WAIT(2);
        __syncthreads();
        uint32_t stA = sbase + (kt & 3) * 24576;
#pragma unroll
        for (int ks = 0; ks < 2; ks++) {
            uint32_t A[2][4], B1f[4][2], B3f[4][2];
#pragma unroll
            for (int f = 0; f < 2; f++) {
                uint32_t ad = stA + (rowA + f * 16) * 64 + (((ks * 2 + cbA) ^ selA) << 4);
                LDSM4(A[f][0], A[f][1], A[f][2], A[f][3], ad);
            }
#pragma unroll
            for (int p = 0; p < 2; p++) {
                uint32_t boff = (rowB + p * 16) * 64 + (((ks * 2 + cbB) ^ selB) << 4);
                LDSM4(B1f[2 * p][0], B1f[2 * p][1], B1f[2 * p + 1][0], B1f[2 * p + 1][1],
                      stA + 8192 + boff);
                LDSM4(B3f[2 * p][0], B3f[2 * p][1], B3f[2 * p + 1][0], B3f[2 * p + 1][1],
                      stA + 16384 + boff);
            }
#pragma unroll
            for (int f = 0; f < 2; f++)
#pragma unroll
                for (int g = 0; g < 4; g++) {
                    MMA16816(acc1[f][g], A[f], B1f[g]);
                    MMA16816(acc3[f][g], A[f], B3f[g]);
                }
        }
        int nk = kt + 3;
        if (nk < KT) {
            uint32_t st = sbase + (nk & 3) * 24576;
            int col = nk * 32 + cp * 8;
            CP16(st +         dOff, arow  + col);
            CP16(st +  8192 + dOff, b1row + col);
            CP16(st + 16384 + dOff, b3row + col);
        }
        CP_COMMIT();
    }

    const int rg = lane >> 2, cq = (lane & 3) * 2;
    const int off = g_off[e];
#pragma unroll
    for (int f = 0; f < 2; f++) {
#pragma unroll
        for (int half = 0; half < 2; half++) {
            int mrel = wm * 32 + f * 16 + rg + half * 8;
            int srow = m0 + mrel;
            if (srow < cnt) {
                __nv_bfloat16* rowp = g_hs + (size_t)(off + srow) * K2D;
#pragma unroll
                for (int g = 0; g < 4; g++) {
                    int n = n0 + wn * 32 + g * 8 + cq;
                    float h0 = fmaxf(acc1[f][g][half * 2 + 0], 0.f) * acc3[f][g][half * 2 + 0];
                    float h1 = fmaxf(acc1[f][g][half * 2 + 1], 0.f) * acc3[f][g][half * 2 + 1];
                    __nv_bfloat16 hh0, hl0, hh1, hl1;
                    bsplit(h0, hh0, hl0); bsplit(h1, hh1, hl1);
                    __nv_bfloat162 hi; hi.x = hh0; hi.y = hh1;
                    __nv_bfloat162 lo; lo.x = hl0; lo.y = hl1;
                    *(__nv_bfloat162*)&rowp[n]          = hi;
                    *(__nv_bfloat162*)&rowp[FF + n]     = hi;
                    *(__nv_bfloat162*)&rowp[2 * FF + n] = lo;
                }
            }
        }
    }
}

// ------------------------- launch -------------------------------------------
extern "C" void kernel_launch(void* const* d_in, const int* in_sizes, int n_in,
                              void* d_out, int out_size) {
    const float* x   = (const float*)d_in[0];
    const float* gw1 = (const float*)d_in[1];
    const float* gb1 = (const float*)d_in[2];
    const float* gw2 = (const float*)d_in[3];
    const float* gb2 = (const float*)d_in[4];
    const float* w1  = (const float*)d_in[5];
    const float* w3  = (const float*)d_in[6];
    const float* w2  = (const float*)d_in[7];
    float* out    = (float*)d_out;
    float* logits = out + (size_t)TT * HH;

    __nv_bfloat16 *d_xs, *d_gw1s, *d_w1s, *d_w3s, *d_w2s, *d_hs;
    cudaGetSymbolAddress((void**)&d_xs,   g_xs);
    cudaGetSymbolAddress((void**)&d_gw1s, g_gw1s);
    cudaGetSymbolAddress((void**)&d_w1s,  g_w1s);
    cudaGetSymbolAddress((void**)&d_w3s,  g_w3s);
    cudaGetSymbolAddress((void**)&d_w2s,  g_w2s);
    cudaGetSymbolAddress((void**)&d_hs,   g_hs);
    float* d_act;
    cudaGetSymbolAddress((void**)&d_act, g_act);

    const int SMEM  = 4 * 16384;    // 64KB  (gate/down)
    const int SMEMF = 4 * 24576;    // 96KB  (fused up)
    cudaFuncSetAttribute(k_gemm<0>, cudaFuncAttributeMaxDynamicSharedMemorySize, SMEM);
    cudaFuncSetAttribute(k_gemm<2>, cudaFuncAttributeMaxDynamicSharedMemorySize, SMEM);
    cudaFuncSetAttribute(k_upfused, cudaFuncAttributeMaxDynamicSharedMemorySize, SMEMF);

    int nz = TT * HH;
    k_reset<<<(nz + 255) / 256, 256>>>(out, nz);
    k_splitX<<<(TT * HH + 255) / 256, 256>>>(x);
    k_trsplit<<<dim3(GHD / 32, HH / 64, 1),  dim3(32, 8)>>>(gw1, d_gw1s, HH, GHD);
    k_trsplit<<<dim3(FF / 32,  HH / 64, NE), dim3(32, 8)>>>(w1,  d_w1s,  HH, FF);
    k_trsplit<<<dim3(FF / 32,  HH / 64, NE), dim3(32, 8)>>>(w3,  d_w3s,  HH, FF);
    k_trsplit<<<dim3(HH / 32,  FF / 64, NE), dim3(32, 8)>>>(w2,  d_w2s,  FF, HH);

    // gate: [4096,3072] @ [1024,3072]^T -> g_act (bias+ELU)
    k_gemm<0><<<dim3(GHD / 128, TT / 128, 1), 256, SMEM>>>(d_xs, d_gw1s, K2G, d_act, gb1);
    k_route<<<TT / 8, 256>>>(gw2, gb2, logits);
    k_off_k<<<1, 32>>>();
    // fused up: gathered [cnt,3072] @ ([2048,3072]^T x2) -> g_hs (split)
    k_upfused<<<dim3(FF / 128, TT / 128, NE), 512, SMEMF>>>(d_xs);
    // down: [cnt,6144] @ [1024,6144]^T -> weighted scatter-add into out
    k_gemm<2><<<dim3(HH / 128, TT / 128, NE), 256, SMEM>>>(d_hs, d_w2s, K2D, out, nullptr);
}

// round 9
// speedup vs baseline: 2.7401x; 1.1649x over previous
#include <cuda_runtime.h>
#include <cuda_bf16.h>
#include <math.h>
#include <cstdint>

// Problem constants
#define TT   4096
#define HH   1024
#define FF   2048
#define NE   8
#define GHD  1024
#define CROWS 8192     // total compact expert rows = 2*TT (top-2 exact)

// ------------------------- device scratch (no allocs allowed) ---------------
// 2-zone split layout: row = [hi(0..K) | lo(K..2K)]
__device__ __nv_bfloat16 g_xs  [(size_t)TT * 2 * HH];      // X split [T, 2H]
__device__ __nv_bfloat16 g_gw1s[(size_t)GHD * 2 * HH];     // gw1^T split [N, 2K]
__device__ __nv_bfloat16 g_w1s [(size_t)NE * FF * 2 * HH];
__device__ __nv_bfloat16 g_w3s [(size_t)NE * FF * 2 * HH];
__device__ __nv_bfloat16 g_w2s [(size_t)NE * HH * 2 * FF];
__device__ __nv_bfloat16 g_hs  [(size_t)CROWS * 2 * FF];   // expert hidden split
__device__ float g_act[(size_t)TT * GHD];                  // gate hidden (fp32)
__device__ int   g_idx[NE * TT];
__device__ float g_wt [NE * TT];
__device__ int   g_cnt[NE];
__device__ int   g_off[NE];

// ------------------------- PTX helpers --------------------------------------
__device__ __forceinline__ uint32_t smem_u32(const void* p) {
    uint32_t a;
    asm("{ .reg .u64 t; cvta.to.shared.u64 t, %1; cvt.u32.u64 %0, t; }" : "=r"(a) : "l"(p));
    return a;
}
#define CP16(dst, src) \
    asm volatile("cp.async.cg.shared.global [%0], [%1], 16;" :: "r"(dst), "l"(src))
#define CP_COMMIT() asm volatile("cp.async.commit_group;" ::: "memory")
#define CP_WAIT(n)  asm volatile("cp.async.wait_group %0;" :: "n"(n) : "memory")

#define LDSM4(r0, r1, r2, r3, addr) \
    asm volatile("ldmatrix.sync.aligned.m8n8.x4.shared.b16 {%0,%1,%2,%3}, [%4];" \
        : "=r"(r0), "=r"(r1), "=r"(r2), "=r"(r3) : "r"(addr))

#define MMA16816(d, a, b) \
    asm volatile("mma.sync.aligned.m16n8k16.row.col.f32.bf16.bf16.f32 " \
        "{%0,%1,%2,%3}, {%4,%5,%6,%7}, {%8,%9}, {%0,%1,%2,%3};" \
        : "+f"((d)[0]), "+f"((d)[1]), "+f"((d)[2]), "+f"((d)[3]) \
        : "r"((a)[0]), "r"((a)[1]), "r"((a)[2]), "r"((a)[3]), "r"((b)[0]), "r"((b)[1]))

__device__ __forceinline__ void bsplit(float v, __nv_bfloat16& h, __nv_bfloat16& l) {
    h = __float2bfloat16_rn(v);
    l = __float2bfloat16_rn(v - __bfloat162float(h));
}

// ------------------------- small kernels ------------------------------------
__global__ void k_reset(float* __restrict__ out, int n) {
    int i = blockIdx.x * blockDim.x + threadIdx.x;
    if (i < n) out[i] = 0.0f;
    if (i < NE) g_cnt[i] = 0;
}

// X [T,H] fp32 -> g_xs [T,2H] zones [hi | lo]
__global__ void k_splitX(const float* __restrict__ X) {
    int i = blockIdx.x * blockDim.x + threadIdx.x;
    if (i >= TT * HH) return;
    int t = i >> 10, k = i & 1023;
    __nv_bfloat16 h, l; bsplit(X[i], h, l);
    __nv_bfloat16* r = g_xs + (size_t)t * 2 * HH;
    r[k] = h; r[HH + k] = l;
}

// in [R,C] fp32 (slab z) -> out [C,2R] zones [hi | lo]; 16B stores
__global__ void k_trsplit(const float* __restrict__ in, __nv_bfloat16* __restrict__ out,
                          int R, int C) {
    __shared__ float t[64][33];
    size_t ioff = (size_t)blockIdx.z * R * C;
    size_t ooff = (size_t)blockIdx.z * C * 2 * R;
    int c0 = blockIdx.x * 32, r0 = blockIdx.y * 64;
    int tx = threadIdx.x, ty = threadIdx.y;
#pragma unroll
    for (int i = ty; i < 64; i += 8)
        t[i][tx] = in[ioff + (size_t)(r0 + i) * C + c0 + tx];
    __syncthreads();
    int tid = ty * 32 + tx;
    int cidx = tid >> 3;            // 0..31
    int k0   = (tid & 7) * 8;       // 0..56
    uint32_t H[4], L[4];
#pragma unroll
    for (int j = 0; j < 4; j++) {
        float v0 = t[k0 + 2 * j + 0][cidx];
        float v1 = t[k0 + 2 * j + 1][cidx];
        __nv_bfloat16 h0, l0, h1, l1;
        bsplit(v0, h0, l0); bsplit(v1, h1, l1);
        __nv_bfloat162 hp; hp.x = h0; hp.y = h1;
        __nv_bfloat162 lp; lp.x = l0; lp.y = l1;
        H[j] = *(uint32_t*)&hp; L[j] = *(uint32_t*)&lp;
    }
    __nv_bfloat16* orow = out + ooff + (size_t)(c0 + cidx) * 2 * R;
    int k = r0 + k0;
    *(uint4*)&orow[k]     = make_uint4(H[0], H[1], H[2], H[3]);
    *(uint4*)&orow[R + k] = make_uint4(L[0], L[1], L[2], L[3]);
}

// routing: one warp per token (reads fp32 g_act)
__global__ void k_route(const float* __restrict__ W2, const float* __restrict__ b2,
                        float* __restrict__ logits_out) {
    int gt = blockIdx.x * (blockDim.x >> 5) + (threadIdx.x >> 5);
    int lane = threadIdx.x & 31;
    if (gt >= TT) return;
    const float* g = g_act + (size_t)gt * GHD;
    float s[NE] = {};
    for (int k = lane; k < GHD; k += 32) {
        float gv = g[k];
        const float* wr = W2 + (size_t)k * NE;
#pragma unroll
        for (int e = 0; e < NE; e++) s[e] = fmaf(gv, wr[e], s[e]);
    }
#pragma unroll
    for (int o = 16; o; o >>= 1)
#pragma unroll
        for (int e = 0; e < NE; e++) s[e] += __shfl_down_sync(0xffffffffu, s[e], o);
    if (lane == 0) {
        float lg[NE]; float mx = -1e30f;
#pragma unroll
        for (int e = 0; e < NE; e++) {
            lg[e] = s[e] + b2[e];
            logits_out[(size_t)gt * NE + e] = lg[e];
            mx = fmaxf(mx, lg[e]);
        }
        float ex[NE], S = 0.0f;
#pragma unroll
        for (int e = 0; e < NE; e++) { ex[e] = expf(lg[e] - mx); S += ex[e]; }
        float p[NE];
#pragma unroll
        for (int e = 0; e < NE; e++) p[e] = ex[e] / S;
        int i0 = 0;
#pragma unroll
        for (int e = 1; e < NE; e++) if (p[e] > p[i0]) i0 = e;
        int i1 = -1;
#pragma unroll
        for (int e = 0; e < NE; e++) {
            if (e == i0) continue;
            if (i1 < 0 || p[e] > p[i1]) i1 = e;
        }
        float tw = p[i0] + p[i1];
        int q0 = atomicAdd(&g_cnt[i0], 1);
        g_idx[i0 * TT + q0] = gt;  g_wt[i0 * TT + q0] = p[i0] / tw;
        int q1 = atomicAdd(&g_cnt[i1], 1);
        g_idx[i1 * TT + q1] = gt;  g_wt[i1 * TT + q1] = p[i1] / tw;
    }
}

__global__ void k_off_k() {
    if (threadIdx.x == 0) {
        int a = 0;
#pragma unroll
        for (int e = 0; e < NE; e++) { g_off[e] = a; a += g_cnt[e]; }
    }
}

// ------------------------- split-precision GEMM (gate / down) ----------------
// C = A@B^T with A,B in 2-zone hi/lo layout; 3 products Ah·Bh + Ah·Bl + Al·Bh.
// 512 thr, CTA 128x128, warp 32x32 (4x4), 3-stage cp.async (32KB/stage).
// MODE 0: gate (out=g_act, bias+ELU). MODE 2: down (out += w*C scatter).
template <int MODE>
__global__ void __launch_bounds__(512)
k_gemm(const __nv_bfloat16* __restrict__ Ab, const __nv_bfloat16* __restrict__ Bb,
       int K, float* __restrict__ outp, const float* __restrict__ bias) {
    const int e = blockIdx.z;
    const int m0 = blockIdx.y * 128, n0 = blockIdx.x * 128;
    int cnt, hoff = 0;
    if (MODE == 0) cnt = TT;
    else {
        cnt = g_cnt[e];
        if (m0 >= cnt) return;
        hoff = g_off[e];
    }
    const int bRows = (MODE == 2) ? HH : GHD;
    const __nv_bfloat16* Bex = Bb + (MODE == 0 ? (size_t)0 : (size_t)e * bRows * 2 * K);

    extern __shared__ char sm[];
    const uint32_t sbase = smem_u32(sm);
    const int tid = threadIdx.x;
    const int lane = tid & 31, wid = tid >> 5;
    const int wm = wid & 3, wn = wid >> 2;      // 4x4 warps, warp tile 32x32

    // loader: lr = row 0..127, cp = 16B chunk 0..3; 1 CP16 per buffer per thread
    const int lr = tid >> 2, cp = tid & 3;
    const __nv_bfloat16* arow;
    if (MODE == 0) {
        arow = Ab + (size_t)(m0 + lr) * 2 * K;
    } else {
        int rr = hoff + m0 + lr; if (rr > CROWS - 1) rr = CROWS - 1;
        arow = Ab + (size_t)rr * 2 * K;
    }
    const __nv_bfloat16* brow = Bex + (size_t)(n0 + lr) * 2 * K;
    const int sel = (lr >> 1) & 3;
    const uint32_t dOff = lr * 64 + ((cp ^ sel) << 4);

    const int t8 = lane >> 3, i7 = lane & 7;
    const int rowA = wm * 32 + (t8 & 1) * 8 + i7;
    const int rowB = wn * 32 + (t8 >> 1) * 8 + i7;
    const int selA = (rowA >> 1) & 3, cbA = t8 >> 1;
    const int selB = (rowB >> 1) & 3, cbB = t8 & 1;

    float acc[2][4][4] = {};
    const int KT = K >> 5;
    // stage buffers: Ah +0, Al +8K, Bh +16K, Bl +24K (32KB/stage, 3 stages)
#pragma unroll
    for (int s = 0; s < 2; s++) {
        uint32_t st = sbase + s * 32768;
        int col = s * 32 + cp * 8;
        CP16(st +         dOff, arow + col);
        CP16(st +  8192 + dOff, arow + K + col);
        CP16(st + 16384 + dOff, brow + col);
        CP16(st + 24576 + dOff, brow + K + col);
        CP_COMMIT();
    }

    for (int kt = 0; kt < KT; kt++) {
        CP_WAIT(1);
        __syncthreads();
        uint32_t st = sbase + (kt % 3) * 32768;
#pragma unroll
        for (int ks = 0; ks < 2; ks++) {
            uint32_t Ah[2][4], Al[2][4], Bh[4][2], Bl[4][2];
#pragma unroll
            for (int f = 0; f < 2; f++) {
                uint32_t aoff = (rowA + f * 16) * 64 + (((ks * 2 + cbA) ^ selA) << 4);
                LDSM4(Ah[f][0], Ah[f][1], Ah[f][2], Ah[f][3], st + aoff);
                LDSM4(Al[f][0], Al[f][1], Al[f][2], Al[f][3], st + 8192 + aoff);
            }
#pragma unroll
            for (int p = 0; p < 2; p++) {
                uint32_t boff = (rowB + p * 16) * 64 + (((ks * 2 + cbB) ^ selB) << 4);
                LDSM4(Bh[2 * p][0], Bh[2 * p][1], Bh[2 * p + 1][0], Bh[2 * p + 1][1],
                      st + 16384 + boff);
                LDSM4(Bl[2 * p][0], Bl[2 * p][1], Bl[2 * p + 1][0], Bl[2 * p + 1][1],
                      st + 24576 + boff);
            }
#pragma unroll
            for (int f = 0; f < 2; f++)
#pragma unroll
                for (int g = 0; g < 4; g++) {
                    MMA16816(acc[f][g], Ah[f], Bh[g]);
                    MMA16816(acc[f][g], Ah[f], Bl[g]);
                    MMA16816(acc[f][g], Al[f], Bh[g]);
                }
        }
        int nk = kt + 2;
        if (nk < KT) {
            uint32_t stw = sbase + (nk % 3) * 32768;
            int col = nk * 32 + cp * 8;
            CP16(stw +         dOff, arow + col);
            CP16(stw +  8192 + dOff, arow + K + col);
            CP16(stw + 16384 + dOff, brow + col);
            CP16(stw + 24576 + dOff, brow + K + col);
        }
        CP_COMMIT();
    }

    const int rg = lane >> 2, cq = (lane & 3) * 2;
#pragma unroll
    for (int f = 0; f < 2; f++) {
#pragma unroll
        for (int half = 0; half < 2; half++) {
            int mrel = wm * 32 + f * 16 + rg + half * 8;
#pragma unroll
            for (int g = 0; g < 4; g++) {
                float v0 = acc[f][g][half * 2 + 0];
                float v1 = acc[f][g][half * 2 + 1];
                int n = n0 + wn * 32 + g * 8 + cq;
                if (MODE == 0) {
                    int m = m0 + mrel;
                    float a0 = v0 + bias[n], a1 = v1 + bias[n + 1];
                    a0 = a0 > 0.f ? a0 : expm1f(a0);
                    a1 = a1 > 0.f ? a1 : expm1f(a1);
                    *(float2*)&g_act[(size_t)m * GHD + n] = make_float2(a0, a1);
                } else {
                    int slot = m0 + mrel;
                    if (slot < cnt) {
                        int tok = g_idx[e * TT + slot];
                        float w = g_wt[e * TT + slot];
                        float* orow = outp + (size_t)tok * HH + n;
                        atomicAdd(&orow[0], w * v0);
                        atomicAdd(&orow[1], w * v1);
                    }
                }
            }
        }
    }
}

// ------------------- fused up GEMM: h = relu(Xg@w1)*(Xg@w3) ------------------
// 512 thr, CTA 128(M) x [128(w1)+128(w3)], warp 32x(32+32), 3-stage (48KB/stage).
__global__ void __launch_bounds__(512)
k_upfused(const __nv_bfloat16* __restrict__ Ab) {
    const int e = blockIdx.z;
    const int cnt = g_cnt[e];
    const int m0 = blockIdx.y * 128;
    if (m0 >= cnt) return;
    const int n0 = blockIdx.x * 128;

    extern __shared__ char sm[];
    const uint32_t sbase = smem_u32(sm);
    const int tid = threadIdx.x;
    const int lane = tid & 31, wid = tid >> 5;
    const int wm = wid & 3, wn = wid >> 2;

    const int lr = tid >> 2, cp = tid & 3;
    int slot = m0 + lr; if (slot >= cnt) slot = cnt - 1;
    const __nv_bfloat16* arow  = Ab + (size_t)g_idx[e * TT + slot] * 2 * HH;
    const __nv_bfloat16* b1row = g_w1s + (size_t)e * FF * 2 * HH + (size_t)(n0 + lr) * 2 * HH;
    const __nv_bfloat16* b3row = g_w3s + (size_t)e * FF * 2 * HH + (size_t)(n0 + lr) * 2 * HH;
    const int sel = (lr >> 1) & 3;
    const uint32_t dOff = lr * 64 + ((cp ^ sel) << 4);

    const int t8 = lane >> 3, i7 = lane & 7;
    const int rowA = wm * 32 + (t8 & 1) * 8 + i7;
    const int rowB = wn * 32 + (t8 >> 1) * 8 + i7;
    const int selA = (rowA >> 1) & 3, cbA = t8 >> 1;
    const int selB = (rowB >> 1) & 3, cbB = t8 & 1;

    float acc1[2][4][4] = {}, acc3[2][4][4] = {};
    const int KT = HH >> 5;   // 32
    // stage: Ah +0, Al +8K, B1h +16K, B1l +24K, B3h +32K, B3l +40K (48KB)
#pragma unroll
    for (int s = 0; s < 2; s++) {
        uint32_t st = sbase + s * 49152;
        int col = s * 32 + cp * 8;
        CP16(st +         dOff, arow + col);
        CP16(st +  8192 + dOff, arow + HH + col);
        CP16(st + 16384 + dOff, b1row + col);
        CP16(st + 24576 + dOff, b1row + HH + col);
        CP16(st + 32768 + dOff, b3row + col);
        CP16(st + 40960 + dOff, b3row + HH + col);
        CP_COMMIT();
    }

    for (int kt = 0; kt < KT; kt++) {
        CP_WAIT(1);
        __syncthreads();
        uint32_t st = sbase + (kt % 3) * 49152;
#pragma unroll
        for (int ks = 0; ks < 2; ks++) {
            uint32_t Ah[2][4], Al[2][4];
#pragma unroll
            for (int f = 0; f < 2; f++) {
                uint32_t aoff = (rowA + f * 16) * 64 + (((ks * 2 + cbA) ^ selA) << 4);
                LDSM4(Ah[f][0], Ah[f][1], Ah[f][2], Ah[f][3], st + aoff);
                LDSM4(Al[f][0], Al[f][1], Al[f][2], Al[f][3], st + 8192 + aoff);
            }
            {   // w1 products
                uint32_t Bh[4][2], Bl[4][2];
#pragma unroll
                for (int p = 0; p < 2; p++) {
                    uint32_t boff = (rowB + p * 16) * 64 + (((ks * 2 + cbB) ^ selB) << 4);
                    LDSM4(Bh[2 * p][0], Bh[2 * p][1], Bh[2 * p + 1][0], Bh[2 * p + 1][1],
                          st + 16384 + boff);
                    LDSM4(Bl[2 * p][0], Bl[2 * p][1], Bl[2 * p + 1][0], Bl[2 * p + 1][1],
                          st + 24576 + boff);
                }
#pragma unroll
                for (int f = 0; f < 2; f++)
#pragma unroll
                    for (int g = 0; g < 4; g++) {
                        MMA16816(acc1[f][g], Ah[f], Bh[g]);
                        MMA16816(acc1[f][g], Ah[f], Bl[g]);
                        MMA16816(acc1[f][g], Al[f], Bh[g]);
                    }
            }
            {   // w3 products
                uint32_t Bh[4][2], Bl[4][2];
#pragma unroll
                for (int p = 0; p < 2; p++) {
                    uint32_t boff = (rowB + p * 16) * 64 + (((ks * 2 + cbB) ^ selB) << 4);
                    LDSM4(Bh[2 * p][0], Bh[2 * p][1], Bh[2 * p + 1][0], Bh[2 * p + 1][1],
                          st + 32768 + boff);
                    LDSM4(Bl[2 * p][0], Bl[2 * p][1], Bl[2 * p + 1][0], Bl[2 * p + 1][1],
                          st + 40960 + boff);
                }
#pragma unroll
                for (int f = 0; f < 2; f++)
#pragma unroll
                    for (int g = 0; g < 4; g++) {
                        MMA16816(acc3[f][g], Ah[f], Bh[g]);
                        MMA16816(acc3[f][g], Ah[f], Bl[g]);
                        MMA16816(acc3[f][g], Al[f], Bh[g]);
                    }
            }
        }
        int nk = kt + 2;
        if (nk < KT) {
            uint32_t stw = sbase + (nk % 3) * 49152;
            int col = nk * 32 + cp * 8;
            CP16(stw +         dOff, arow + col);
            CP16(stw +  8192 + dOff, arow + HH + col);
            CP16(stw + 16384 + dOff, b1row + col);
            CP16(stw + 24576 + dOff, b1row + HH + col);
            CP16(stw + 32768 + dOff, b3row + col);
            CP16(stw + 40960 + dOff, b3row + HH + col);
        }
        CP_COMMIT();
    }

    const int rg = lane >> 2, cq = (lane & 3) * 2;
    const int off = g_off[e];
#pragma unroll
    for (int f = 0; f < 2; f++) {
#pragma unroll
        for (int half = 0; half < 2; half++) {
            int mrel = wm * 32 + f * 16 + rg + half * 8;
            int srow = m0 + mrel;
            if (srow < cnt) {
                __nv_bfloat16* rowp = g_hs + (size_t)(off + srow) * 2 * FF;
#pragma unroll
                for (int g = 0; g < 4; g++) {
                    int n = n0 + wn * 32 + g * 8 + cq;
                    float h0 = fmaxf(acc1[f][g][half * 2 + 0], 0.f) * acc3[f][g][half * 2 + 0];
                    float h1 = fmaxf(acc1[f][g][half * 2 + 1], 0.f) * acc3[f][g][half * 2 + 1];
                    __nv_bfloat16 hh0, hl0, hh1, hl1;
                    bsplit(h0, hh0, hl0); bsplit(h1, hh1, hl1);
                    __nv_bfloat162 hi; hi.x = hh0; hi.y = hh1;
                    __nv_bfloat162 lo; lo.x = hl0; lo.y = hl1;
                    *(__nv_bfloat162*)&rowp[n]      = hi;
                    *(__nv_bfloat162*)&rowp[FF + n] = lo;
                }
            }
        }
    }
}

// ------------------------- launch -------------------------------------------
extern "C" void kernel_launch(void* const* d_in, const int* in_sizes, int n_in,
                              void* d_out, int out_size) {
    const float* x   = (const float*)d_in[0];
    const float* gw1 = (const float*)d_in[1];
    const float* gb1 = (const float*)d_in[2];
    const float* gw2 = (const float*)d_in[3];
    const float* gb2 = (const float*)d_in[4];
    const float* w1  = (const float*)d_in[5];
    const float* w3  = (const float*)d_in[6];
    const float* w2  = (const float*)d_in[7];
    float* out    = (float*)d_out;
    float* logits = out + (size_t)TT * HH;

    __nv_bfloat16 *d_xs, *d_gw1s, *d_w1s, *d_w3s, *d_w2s, *d_hs;
    cudaGetSymbolAddress((void**)&d_xs,   g_xs);
    cudaGetSymbolAddress((void**)&d_gw1s, g_gw1s);
    cudaGetSymbolAddress((void**)&d_w1s,  g_w1s);
    cudaGetSymbolAddress((void**)&d_w3s,  g_w3s);
    cudaGetSymbolAddress((void**)&d_w2s,  g_w2s);
    cudaGetSymbolAddress((void**)&d_hs,   g_hs);
    float* d_act;
    cudaGetSymbolAddress((void**)&d_act, g_act);

    const int SMEM  = 3 * 32768;    // 96KB  (gate/down)
    const int SMEMF = 3 * 49152;    // 144KB (fused up)
    cudaFuncSetAttribute(k_gemm<0>, cudaFuncAttributeMaxDynamicSharedMemorySize, SMEM);
    cudaFuncSetAttribute(k_gemm<2>, cudaFuncAttributeMaxDynamicSharedMemorySize, SMEM);
    cudaFuncSetAttribute(k_upfused, cudaFuncAttributeMaxDynamicSharedMemorySize, SMEMF);

    int nz = TT * HH;
    k_reset<<<(nz + 255) / 256, 256>>>(out, nz);
    k_splitX<<<(TT * HH + 255) / 256, 256>>>(x);
    k_trsplit<<<dim3(GHD / 32, HH / 64, 1),  dim3(32, 8)>>>(gw1, d_gw1s, HH, GHD);
    k_trsplit<<<dim3(FF / 32,  HH / 64, NE), dim3(32, 8)>>>(w1,  d_w1s,  HH, FF);
    k_trsplit<<<dim3(FF / 32,  HH / 64, NE), dim3(32, 8)>>>(w3,  d_w3s,  HH, FF);
    k_trsplit<<<dim3(HH / 32,  FF / 64, NE), dim3(32, 8)>>>(w2,  d_w2s,  FF, HH);

    // gate: X @ gw1^T (3-product split) -> g_act (bias+ELU)
    k_gemm<0><<<dim3(GHD / 128, TT / 128, 1), 512, SMEM>>>(d_xs, d_gw1s, HH, d_act, gb1);
    k_route<<<TT / 8, 256>>>(gw2, gb2, logits);
    k_off_k<<<1, 32>>>();
    // fused up: gathered X @ (w1,w3) -> g_hs (2-zone split)
    k_upfused<<<dim3(FF / 128, TT / 128, NE), 512, SMEMF>>>(d_xs);
    // down: h @ w2^T -> weighted scatter-add into out
    k_gemm<2><<<dim3(HH / 128, TT / 128, NE), 512, SMEM>>>(d_hs, d_w2s, FF, out, nullptr);
}

// round 11
// speedup vs baseline: 2.8997x; 1.0583x over previous
#include <cuda_runtime.h>
#include <cuda_bf16.h>
#include <math.h>
#include <cstdint>

// Problem constants
#define TT   4096
#define HH   1024
#define FF   2048
#define NE   8
#define GHD  1024
#define CROWS 8192
#define QM   32512.0f    // 127*256: 15-bit quant full-scale

// ------------------------- device scratch -----------------------------------
__device__ __nv_bfloat16 g_xs  [(size_t)TT * 2 * HH];      // X bf16 split (gate)
__device__ __nv_bfloat16 g_gw1s[(size_t)GHD * 2 * HH];     // gw1^T bf16 split
__device__ __nv_bfloat16 g_w2s [(size_t)NE * HH * 2 * FF]; // w2^T bf16 split
__device__ __nv_bfloat16 g_hs  [(size_t)CROWS * 2 * FF];   // h bf16 split
__device__ int8_t g_xq [(size_t)TT * 2 * HH];              // X int8 [ah|al] (up)
__device__ int8_t g_w1q[(size_t)NE * FF * 2 * HH];         // w1^T int8 [N,[ah K|al K]]
__device__ int8_t g_w3q[(size_t)NE * FF * 2 * HH];
__device__ float g_sx [TT];                                // dequant scales (max/QM)
__device__ float g_sw1[NE * FF];
__device__ float g_sw3[NE * FF];
__device__ float g_y  [(size_t)CROWS * HH];                // down output, compact
__device__ float g_act[(size_t)TT * GHD];
__device__ int   g_idx[NE * TT];
__device__ float g_wt [NE * TT];
__device__ int   g_slot[2 * TT];                           // token -> (e*TT+q) x2
__device__ int   g_cnt[NE];
__device__ int   g_off[NE];

// ------------------------- PTX helpers --------------------------------------
__device__ __forceinline__ uint32_t smem_u32(const void* p) {
    uint32_t a;
    asm("{ .reg .u64 t; cvta.to.shared.u64 t, %1; cvt.u32.u64 %0, t; }" : "=r"(a) : "l"(p));
    return a;
}
#define CP16(dst, src) \
    asm volatile("cp.async.cg.shared.global [%0], [%1], 16;" :: "r"(dst), "l"(src))
#define CP_COMMIT() asm volatile("cp.async.commit_group;" ::: "memory")
#define CP_WAIT(n)  asm volatile("cp.async.wait_group %0;" :: "n"(n) : "memory")

#define LDSM4(r0, r1, r2, r3, addr) \
    asm volatile("ldmatrix.sync.aligned.m8n8.x4.shared.b16 {%0,%1,%2,%3}, [%4];" \
        : "=r"(r0), "=r"(r1), "=r"(r2), "=r"(r3) : "r"(addr))

#define MMA16816(d, a, b) \
    asm volatile("mma.sync.aligned.m16n8k16.row.col.f32.bf16.bf16.f32 " \
        "{%0,%1,%2,%3}, {%4,%5,%6,%7}, {%8,%9}, {%0,%1,%2,%3};" \
        : "+f"((d)[0]), "+f"((d)[1]), "+f"((d)[2]), "+f"((d)[3]) \
        : "r"((a)[0]), "r"((a)[1]), "r"((a)[2]), "r"((a)[3]), "r"((b)[0]), "r"((b)[1]))

#define MMAS8(d, a, b) \
    asm volatile("mma.sync.aligned.m16n8k32.row.col.s32.s8.s8.s32 " \
        "{%0,%1,%2,%3}, {%4,%5,%6,%7}, {%8,%9}, {%0,%1,%2,%3};" \
        : "+r"((d)[0]), "+r"((d)[1]), "+r"((d)[2]), "+r"((d)[3]) \
        : "r"((a)[0]), "r"((a)[1]), "r"((a)[2]), "r"((a)[3]), "r"((b)[0]), "r"((b)[1]))

__device__ __forceinline__ void bsplit(float v, __nv_bfloat16& h, __nv_bfloat16& l) {
    h = __float2bfloat16_rn(v);
    l = __float2bfloat16_rn(v - __bfloat162float(h));
}

// ------------------------- small kernels ------------------------------------
__global__ void k_reset_cnt() { if (threadIdx.x < NE) g_cnt[threadIdx.x] = 0; }

// X fp32 -> bf16 split (gate)
__global__ void k_splitX(const float* __restrict__ X) {
    int i = blockIdx.x * blockDim.x + threadIdx.x;
    if (i >= TT * HH) return;
    int t = i >> 10, k = i & 1023;
    __nv_bfloat16 h, l; bsplit(X[i], h, l);
    __nv_bfloat16* r = g_xs + (size_t)t * 2 * HH;
    r[k] = h; r[HH + k] = l;
}

// X fp32 -> int8 15-bit split per token (up)
__global__ void k_qx(const float* __restrict__ X) {
    int t = blockIdx.x, tid = threadIdx.x;
    __shared__ float red[128];
    const float* xr = X + (size_t)t * HH;
    float v[8], mx = 0.f;
#pragma unroll
    for (int j = 0; j < 8; j++) { v[j] = xr[tid + 128 * j]; mx = fmaxf(mx, fabsf(v[j])); }
    red[tid] = mx; __syncthreads();
    for (int s = 64; s > 0; s >>= 1) {
        if (tid < s) red[tid] = fmaxf(red[tid], red[tid + s]);
        __syncthreads();
    }
    float m = fmaxf(red[0], 1e-20f);
    if (tid == 0) g_sx[t] = m / QM;
    float qmul = QM / m;
    int8_t* r = g_xq + (size_t)t * 2 * HH;
#pragma unroll
    for (int j = 0; j < 8; j++) {
        int q = __float2int_rn(v[j] * qmul);
        int ah = (q + 128) >> 8, al = q - (ah << 8);
        r[tid + 128 * j] = (int8_t)ah;
        r[HH + tid + 128 * j] = (int8_t)al;
    }
}

// per-output-feature absmax of weight [R,C] columns -> dequant scale
__global__ void k_wmax(const float* __restrict__ in, float* __restrict__ sd, int R, int C) {
    int e = blockIdx.z, n = blockIdx.x * 256 + threadIdx.x;
    const float* p = in + (size_t)e * R * C + n;
    float mx = 0.f;
    for (int r = 0; r < R; r++) mx = fmaxf(mx, fabsf(p[(size_t)r * C]));
    sd[e * C + n] = fmaxf(mx, 1e-20f) / QM;
}

// weight [R,C] fp32 -> [C, 2R] int8 zones [ah | al], transposed, scaled
__global__ void k_trquant(const float* __restrict__ in, int8_t* __restrict__ out,
                          const float* __restrict__ sd, int R, int C) {
    __shared__ float t[64][33];
    __shared__ float qm[32];
    int e = blockIdx.z;
    size_t ioff = (size_t)e * R * C, ooff = (size_t)e * C * 2 * R;
    int c0 = blockIdx.x * 32, r0 = blockIdx.y * 64;
    int tx = threadIdx.x, ty = threadIdx.y;
    if (ty == 0) qm[tx] = 1.0f / sd[e * C + c0 + tx];
#pragma unroll
    for (int i = ty; i < 64; i += 8)
        t[i][tx] = in[ioff + (size_t)(r0 + i) * C + c0 + tx];
    __syncthreads();
    int tid = ty * 32 + tx;
    int cidx = tid >> 3, k0 = (tid & 7) * 8;
    float s = qm[cidx];
    uint8_t ahb[8], alb[8];
#pragma unroll
    for (int j = 0; j < 8; j++) {
        int q = __float2int_rn(t[k0 + j][cidx] * s);
        int ah = (q + 128) >> 8, al = q - (ah << 8);
        ahb[j] = (uint8_t)(int8_t)ah; alb[j] = (uint8_t)(int8_t)al;
    }
    int8_t* orow = out + ooff + (size_t)(c0 + cidx) * 2 * R;
    int k = r0 + k0;
    *(uint2*)&orow[k]     = *(uint2*)ahb;
    *(uint2*)&orow[R + k] = *(uint2*)alb;
}

// bf16 split transpose (gw1, w2) — unchanged from R9
__global__ void k_trsplit(const float* __restrict__ in, __nv_bfloat16* __restrict__ out,
                          int R, int C) {
    __shared__ float t[64][33];
    size_t ioff = (size_t)blockIdx.z * R * C;
    size_t ooff = (size_t)blockIdx.z * C * 2 * R;
    int c0 = blockIdx.x * 32, r0 = blockIdx.y * 64;
    int tx = threadIdx.x, ty = threadIdx.y;
#pragma unroll
    for (int i = ty; i < 64; i += 8)
        t[i][tx] = in[ioff + (size_t)(r0 + i) * C + c0 + tx];
    __syncthreads();
    int tid = ty * 32 + tx;
    int cidx = tid >> 3, k0 = (tid & 7) * 8;
    uint32_t H[4], L[4];
#pragma unroll
    for (int j = 0; j < 4; j++) {
        float v0 = t[k0 + 2 * j + 0][cidx];
        float v1 = t[k0 + 2 * j + 1][cidx];
        __nv_bfloat16 h0, l0, h1, l1;
        bsplit(v0, h0, l0); bsplit(v1, h1, l1);
        __nv_bfloat162 hp; hp.x = h0; hp.y = h1;
        __nv_bfloat162 lp; lp.x = l0; lp.y = l1;
        H[j] = *(uint32_t*)&hp; L[j] = *(uint32_t*)&lp;
    }
    __nv_bfloat16* orow = out + ooff + (size_t)(c0 + cidx) * 2 * R;
    int k = r0 + k0;
    *(uint4*)&orow[k]     = make_uint4(H[0], H[1], H[2], H[3]);
    *(uint4*)&orow[R + k] = make_uint4(L[0], L[1], L[2], L[3]);
}

// routing (+ slot map for combine)
__global__ void k_route(const float* __restrict__ W2, const float* __restrict__ b2,
                        float* __restrict__ logits_out) {
    int gt = blockIdx.x * (blockDim.x >> 5) + (threadIdx.x >> 5);
    int lane = threadIdx.x & 31;
    if (gt >= TT) return;
    const float* g = g_act + (size_t)gt * GHD;
    float s[NE] = {};
    for (int k = lane; k < GHD; k += 32) {
        float gv = g[k];
        const float* wr = W2 + (size_t)k * NE;
#pragma unroll
        for (int e = 0; e < NE; e++) s[e] = fmaf(gv, wr[e], s[e]);
    }
#pragma unroll
    for (int o = 16; o; o >>= 1)
#pragma unroll
        for (int e = 0; e < NE; e++) s[e] += __shfl_down_sync(0xffffffffu, s[e], o);
    if (lane == 0) {
        float lg[NE]; float mx = -1e30f;
#pragma unroll
        for (int e = 0; e < NE; e++) {
            lg[e] = s[e] + b2[e];
            logits_out[(size_t)gt * NE + e] = lg[e];
            mx = fmaxf(mx, lg[e]);
        }
        float ex[NE], S = 0.0f;
#pragma unroll
        for (int e = 0; e < NE; e++) { ex[e] = expf(lg[e] - mx); S += ex[e]; }
        float p[NE];
#pragma unroll
        for (int e = 0; e < NE; e++) p[e] = ex[e] / S;
        int i0 = 0;
#pragma unroll
        for (int e = 1; e < NE; e++) if (p[e] > p[i0]) i0 = e;
        int i1 = -1;
#pragma unroll
        for (int e = 0; e < NE; e++) {
            if (e == i0) continue;
            if (i1 < 0 || p[e] > p[i1]) i1 = e;
        }
        float tw = p[i0] + p[i1];
        int q0 = atomicAdd(&g_cnt[i0], 1);
        g_idx[i0 * TT + q0] = gt;  g_wt[i0 * TT + q0] = p[i0] / tw;
        g_slot[2 * gt + 0] = i0 * TT + q0;
        int q1 = atomicAdd(&g_cnt[i1], 1);
        g_idx[i1 * TT + q1] = gt;  g_wt[i1 * TT + q1] = p[i1] / tw;
        g_slot[2 * gt + 1] = i1 * TT + q1;
    }
}

__global__ void k_off_k() {
    if (threadIdx.x == 0) {
        int a = 0;
#pragma unroll
        for (int e = 0; e < NE; e++) { g_off[e] = a; a += g_cnt[e]; }
    }
}

// combine: out[t] = w0*y[row0] + w1*y[row1]
__global__ void k_combine(float* __restrict__ out) {
    int i = blockIdx.x * 256 + threadIdx.x;        // over TT*HH/4
    if (i >= TT * (HH / 4)) return;
    int t = i / (HH / 4), n4 = (i % (HH / 4)) * 4;
    int s0 = g_slot[2 * t], s1 = g_slot[2 * t + 1];
    float w0 = g_wt[s0], w1 = g_wt[s1];
    int r0 = g_off[s0 >> 12] + (s0 & 4095);
    int r1 = g_off[s1 >> 12] + (s1 & 4095);
    float4 a = *(float4*)&g_y[(size_t)r0 * HH + n4];
    float4 b = *(float4*)&g_y[(size_t)r1 * HH + n4];
    float4 o;
    o.x = w0 * a.x + w1 * b.x; o.y = w0 * a.y + w1 * b.y;
    o.z = w0 * a.z + w1 * b.z; o.w = w0 * a.w + w1 * b.w;
    *(float4*)&out[(size_t)t * HH + n4] = o;
}

// ------------------------- bf16 split GEMM (gate / down) ---------------------
// MODE 0: gate -> g_act (bias+ELU).  MODE 2: down -> g_y compact rows.
template <int MODE>
__global__ void __launch_bounds__(512)
k_gemm(const __nv_bfloat16* __restrict__ Ab, const __nv_bfloat16* __restrict__ Bb,
       int K, float* __restrict__ outp, const float* __restrict__ bias) {
    const int e = blockIdx.z;
    const int m0 = blockIdx.y * 128, n0 = blockIdx.x * 128;
    int cnt, hoff = 0;
    if (MODE == 0) cnt = TT;
    else {
        cnt = g_cnt[e];
        if (m0 >= cnt) return;
        hoff = g_off[e];
    }
    const int bRows = (MODE == 2) ? HH : GHD;
    const __nv_bfloat16* Bex = Bb + (MODE == 0 ? (size_t)0 : (size_t)e * bRows * 2 * K);

    extern __shared__ char sm[];
    const uint32_t sbase = smem_u32(sm);
    const int tid = threadIdx.x;
    const int lane = tid & 31, wid = tid >> 5;
    const int wm = wid & 3, wn = wid >> 2;

    const int lr = tid >> 2, cp = tid & 3;
    const __nv_bfloat16* arow;
    if (MODE == 0) {
        arow = Ab + (size_t)(m0 + lr) * 2 * K;
    } else {
        int rr = hoff + m0 + lr; if (rr > CROWS - 1) rr = CROWS - 1;
        arow = Ab + (size_t)rr * 2 * K;
    }
    const __nv_bfloat16* brow = Bex + (size_t)(n0 + lr) * 2 * K;
    const int sel = (lr >> 1) & 3;
    const uint32_t dOff = lr * 64 + ((cp ^ sel) << 4);

    const int t8 = lane >> 3, i7 = lane & 7;
    const int rowA = wm * 32 + (t8 & 1) * 8 + i7;
    const int rowB = wn * 32 + (t8 >> 1) * 8 + i7;
    const int selA = (rowA >> 1) & 3, cbA = t8 >> 1;
    const int selB = (rowB >> 1) & 3, cbB = t8 & 1;

    float acc[2][4][4] = {};
    const int KT = K >> 5;
#pragma unroll
    for (int s = 0; s < 2; s++) {
        uint32_t st = sbase + s * 32768;
        int col = s * 32 + cp * 8;
        CP16(st +         dOff, arow + col);
        CP16(st +  8192 + dOff, arow + K + col);
        CP16(st + 16384 + dOff, brow + col);
        CP16(st + 24576 + dOff, brow + K + col);
        CP_COMMIT();
    }

    for (int kt = 0; kt < KT; kt++) {
        CP_WAIT(1);
        __syncthreads();
        uint32_t st = sbase + (kt % 3) * 32768;
#pragma unroll
        for (int ks = 0; ks < 2; ks++) {
            uint32_t Ah[2][4], Al[2][4], Bh[4][2], Bl[4][2];
#pragma unroll
            for (int f = 0; f < 2; f++) {
                uint32_t aoff = (rowA + f * 16) * 64 + (((ks * 2 + cbA) ^ selA) << 4);
                LDSM4(Ah[f][0], Ah[f][1], Ah[f][2], Ah[f][3], st + aoff);
                LDSM4(Al[f][0], Al[f][1], Al[f][2], Al[f][3], st + 8192 + aoff);
            }
#pragma unroll
            for (int p = 0; p < 2; p++) {
                uint32_t boff = (rowB + p * 16) * 64 + (((ks * 2 + cbB) ^ selB) << 4);
                LDSM4(Bh[2 * p][0], Bh[2 * p][1], Bh[2 * p + 1][0], Bh[2 * p + 1][1],
                      st + 16384 + boff);
                LDSM4(Bl[2 * p][0], Bl[2 * p][1], Bl[2 * p + 1][0], Bl[2 * p + 1][1],
                      st + 24576 + boff);
            }
#pragma unroll
            for (int f = 0; f < 2; f++)
#pragma unroll
                for (int g = 0; g < 4; g++) {
                    MMA16816(acc[f][g], Ah[f], Bh[g]);
                    MMA16816(acc[f][g], Ah[f], Bl[g]);
                    MMA16816(acc[f][g], Al[f], Bh[g]);
                }
        }
        int nk = kt + 2;
        if (nk < KT) {
            uint32_t stw = sbase + (nk % 3) * 32768;
            int col = nk * 32 + cp * 8;
            CP16(stw +         dOff, arow + col);
            CP16(stw +  8192 + dOff, arow + K + col);
            CP16(stw + 16384 + dOff, brow + col);
            CP16(stw + 24576 + dOff, brow + K + col);
        }
        CP_COMMIT();
    }

    const int rg = lane >> 2, cq = (lane & 3) * 2;
#pragma unroll
    for (int f = 0; f < 2; f++) {
#pragma unroll
        for (int half = 0; half < 2; half++) {
            int mrel = wm * 32 + f * 16 + rg + half * 8;
#pragma unroll
            for (int g = 0; g < 4; g++) {
                float v0 = acc[f][g][half * 2 + 0];
                float v1 = acc[f][g][half * 2 + 1];
                int n = n0 + wn * 32 + g * 8 + cq;
                if (MODE == 0) {
                    int m = m0 + mrel;
                    float a0 = v0 + bias[n], a1 = v1 + bias[n + 1];
                    a0 = a0 > 0.f ? a0 : expm1f(a0);
                    a1 = a1 > 0.f ? a1 : expm1f(a1);
                    *(float2*)&g_act[(size_t)m * GHD + n] = make_float2(a0, a1);
                } else {
                    int slot = m0 + mrel;
                    if (slot < cnt)
                        *(float2*)&g_y[(size_t)(hoff + slot) * HH + n] = make_float2(v0, v1);
                }
            }
        }
    }
}

// ------------------- int8 fused up GEMM: h = relu(Xq@w1q)*(Xq@w3q) -----------
// CTA 128(M) x 64(N) per matrix; 512 thr, 16 warps (4m x 4n), warp 32x16.
// K-stage = 64 (rows of 64B); 3 stages x 32KB. 3 s8 MMAs per k32 per product set.
__global__ void __launch_bounds__(512)
k_upq() {
    const int e = blockIdx.z;
    const int cnt = g_cnt[e];
    const int m0 = blockIdx.y * 128;
    if (m0 >= cnt) return;
    const int n0 = blockIdx.x * 64;

    extern __shared__ char sm[];
    const uint32_t sbase = smem_u32(sm);
    const int tid = threadIdx.x;
    const int lane = tid & 31, wid = tid >> 5;
    const int wm = wid & 3, wn = wid >> 2;     // warp tile 32(M) x 16(N)

    // A loader: 128 rows x 4 chunks(16B) per zone; 2 CP16/thread (ah, al)
    const int ra = tid >> 2, ca = tid & 3;
    int slotL = m0 + ra; if (slotL >= cnt) slotL = cnt - 1;
    const int8_t* arow = g_xq + (size_t)g_idx[e * TT + slotL] * 2 * HH;
    const uint32_t dOffA = ra * 64 + (((ca ^ ((ra >> 1) & 3))) << 4);
    // B loader: 64 rows x 4 chunks x 2 zones = 512; 1 CP16/thread per matrix
    const int rb = (tid & 255) >> 2, cbk = tid & 3, zb = tid >> 8;  // zb in {0,1}
    const int8_t* b1row = g_w1q + (size_t)e * FF * 2 * HH + (size_t)(n0 + rb) * 2 * HH;
    const int8_t* b3row = g_w3q + (size_t)e * FF * 2 * HH + (size_t)(n0 + rb) * 2 * HH;
    const uint32_t dOffB = zb * 4096 + rb * 64 + (((cbk ^ ((rb >> 1) & 3))) << 4);
    const int bsrcz = zb * HH;     // zone offset in source row

    const int t8 = lane >> 3, i7 = lane & 7;
    const int rowA = wm * 32 + (t8 & 1) * 8 + i7;
    const int rowB = wn * 16 + (t8 >> 1) * 8 + i7;
    const int selA = (rowA >> 1) & 3, cbA = t8 >> 1;
    const int selB = (rowB >> 1) & 3, cbB = t8 & 1;

    // int32 accumulators: [f][g][4] ; hh and cross ("x"), per matrix
    int a1hh[2][2][4] = {}, a1x[2][2][4] = {};
    int a3hh[2][2][4] = {}, a3x[2][2][4] = {};

    // stage layout (32KB): Aah 0, Aal 8K, B1(ah|al) 16K..24K, B3(ah|al) 24K..32K
    const int KT = HH / 64;   // 16
#pragma unroll
    for (int s = 0; s < 2; s++) {
        uint32_t st = sbase + s * 32768;
        int k0 = s * 64;
        CP16(st +         dOffA, arow + k0 + ca * 16);
        CP16(st +  8192 + dOffA, arow + HH + k0 + ca * 16);
        CP16(st + 16384 + dOffB, b1row + bsrcz + k0 + cbk * 16);
        CP16(st + 24576 + dOffB, b3row + bsrcz + k0 + cbk * 16);
        CP_COMMIT();
    }

    for (int kt = 0; kt < KT; kt++) {
        CP_WAIT(1);
        __syncthreads();
        uint32_t st = sbase + (kt % 3) * 32768;
#pragma unroll
        for (int ks = 0; ks < 2; ks++) {             // two k32 steps per stage
            uint32_t Ah[2][4], Al[2][4];
#pragma unroll
            for (int f = 0; f < 2; f++) {
                uint32_t aoff = (rowA + f * 16) * 64 + (((ks * 2 + cbA) ^ selA) << 4);
                LDSM4(Ah[f][0], Ah[f][1], Ah[f][2], Ah[f][3], st + aoff);
                LDSM4(Al[f][0], Al[f][1], Al[f][2], Al[f][3], st + 8192 + aoff);
            }
            uint32_t boff = rowB * 64 + (((ks * 2 + cbB) ^ selB) << 4);
            uint32_t B1h[2][2], B1l[2][2], B3h[2][2], B3l[2][2];
            LDSM4(B1h[0][0], B1h[0][1], B1h[1][0], B1h[1][1], st + 16384 + boff);
            LDSM4(B1l[0][0], B1l[0][1], B1l[1][0], B1l[1][1], st + 20480 + boff);
            LDSM4(B3h[0][0], B3h[0][1], B3h[1][0], B3h[1][1], st + 24576 + boff);
            LDSM4(B3l[0][0], B3l[0][1], B3l[1][0], B3l[1][1], st + 28672 + boff);
#pragma unroll
            for (int f = 0; f < 2; f++)
#pragma unroll
                for (int g = 0; g < 2; g++) {
                    MMAS8(a1hh[f][g], Ah[f], B1h[g]);
                    MMAS8(a1x [f][g], Ah[f], B1l[g]);
                    MMAS8(a1x [f][g], Al[f], B1h[g]);
                    MMAS8(a3hh[f][g], Ah[f], B3h[g]);
                    MMAS8(a3x [f][g], Ah[f], B3l[g]);
                    MMAS8(a3x [f][g], Al[f], B3h[g]);
                }
        }
        int nk = kt + 2;
        if (nk < KT) {
            uint32_t stw = sbase + (nk % 3) * 32768;
            int k0 = nk * 64;
            CP16(stw +         dOffA, arow + k0 + ca * 16);
            CP16(stw +  8192 + dOffA, arow + HH + k0 + ca * 16);
            CP16(stw + 16384 + dOffB, b1row + bsrcz + k0 + cbk * 16);
            CP16(stw + 24576 + dOffB, b3row + bsrcz + k0 + cbk * 16);
        }
        CP_COMMIT();
    }

    const int rg = lane >> 2, cq = (lane & 3) * 2;
    const int off = g_off[e];
#pragma unroll
    for (int f = 0; f < 2; f++) {
#pragma unroll
        for (int half = 0; half < 2; half++) {
            int mrel = wm * 32 + f * 16 + rg + half * 8;
            int srow = m0 + mrel;
            if (srow < cnt) {
                float sa = g_sx[g_idx[e * TT + srow]];
                __nv_bfloat16* rowp = g_hs + (size_t)(off + srow) * 2 * FF;
#pragma unroll
                for (int g = 0; g < 2; g++) {
                    int n = n0 + wn * 16 + g * 8 + cq;
                    float s1a = g_sw1[e * FF + n],     s1b = g_sw1[e * FF + n + 1];
                    float s3a = g_sw3[e * FF + n],     s3b = g_sw3[e * FF + n + 1];
                    float u1a = (65536.f * (float)a1hh[f][g][half * 2 + 0]
                               +   256.f * (float)a1x [f][g][half * 2 + 0]) * sa * s1a;
                    float u1b = (65536.f * (float)a1hh[f][g][half * 2 + 1]
                               +   256.f * (float)a1x [f][g][half * 2 + 1]) * sa * s1b;
                    float u3a = (65536.f * (float)a3hh[f][g][half * 2 + 0]
                               +   256.f * (float)a3x [f][g][half * 2 + 0]) * sa * s3a;
                    float u3b = (65536.f * (float)a3hh[f][g][half * 2 + 1]
                               +   256.f * (float)a3x [f][g][half * 2 + 1]) * sa * s3b;
                    float h0 = fmaxf(u1a, 0.f) * u3a;
                    float h1 = fmaxf(u1b, 0.f) * u3b;
                    __nv_bfloat16 hh0, hl0, hh1, hl1;
                    bsplit(h0, hh0, hl0); bsplit(h1, hh1, hl1);
                    __nv_bfloat162 hi; hi.x = hh0; hi.y = hh1;
                    __nv_bfloat162 lo; lo.x = hl0; lo.y = hl1;
                    *(__nv_bfloat162*)&rowp[n]      = hi;
                    *(__nv_bfloat162*)&rowp[FF + n] = lo;
                }
            }
        }
    }
}

// ------------------------- launch -------------------------------------------
extern "C" void kernel_launch(void* const* d_in, const int* in_sizes, int n_in,
                              void* d_out, int out_size) {
    const float* x   = (const float*)d_in[0];
    const float* gw1 = (const float*)d_in[1];
    const float* gb1 = (const float*)d_in[2];
    const float* gw2 = (const float*)d_in[3];
    const float* gb2 = (const float*)d_in[4];
    const float* w1  = (const float*)d_in[5];
    const float* w3  = (const float*)d_in[6];
    const float* w2  = (const float*)d_in[7];
    float* out    = (float*)d_out;
    float* logits = out + (size_t)TT * HH;

    __nv_bfloat16 *d_xs, *d_gw1s, *d_w2s, *d_hs;
    cudaGetSymbolAddress((void**)&d_xs,   g_xs);
    cudaGetSymbolAddress((void**)&d_gw1s, g_gw1s);
    cudaGetSymbolAddress((void**)&d_w2s,  g_w2s);
    cudaGetSymbolAddress((void**)&d_hs,   g_hs);
    int8_t *d_w1q, *d_w3q;
    cudaGetSymbolAddress((void**)&d_w1q, g_w1q);
    cudaGetSymbolAddress((void**)&d_w3q, g_w3q);
    float *d_act, *d_y, *d_sw1, *d_sw3;
    cudaGetSymbolAddress((void**)&d_act, g_act);
    cudaGetSymbolAddress((void**)&d_y,   g_y);
    cudaGetSymbolAddress((void**)&d_sw1, g_sw1);
    cudaGetSymbolAddress((void**)&d_sw3, g_sw3);

    const int SMEM  = 3 * 32768;    // 96KB
    cudaFuncSetAttribute(k_gemm<0>, cudaFuncAttributeMaxDynamicSharedMemorySize, SMEM);
    cudaFuncSetAttribute(k_gemm<2>, cudaFuncAttributeMaxDynamicSharedMemorySize, SMEM);
    cudaFuncSetAttribute(k_upq,     cudaFuncAttributeMaxDynamicSharedMemorySize, SMEM);

    k_reset_cnt<<<1, 32>>>();
    k_splitX<<<(TT * HH + 255) / 256, 256>>>(x);
    k_qx<<<TT, 128>>>(x);
    k_trsplit<<<dim3(GHD / 32, HH / 64, 1),  dim3(32, 8)>>>(gw1, d_gw1s, HH, GHD);
    k_wmax<<<dim3(FF / 256, 1, NE), 256>>>(w1, d_sw1, HH, FF);
    k_wmax<<<dim3(FF / 256, 1, NE), 256>>>(w3, d_sw3, HH, FF);
    k_trquant<<<dim3(FF / 32, HH / 64, NE), dim3(32, 8)>>>(w1, d_w1q, d_sw1, HH, FF);
    k_trquant<<<dim3(FF / 32, HH / 64, NE), dim3(32, 8)>>>(w3, d_w3q, d_sw3, HH, FF);
    k_trsplit<<<dim3(HH / 32, FF / 64, NE), dim3(32, 8)>>>(w2, d_w2s, FF, HH);

    // gate: X @ gw1^T (bf16 3-product) -> g_act (bias+ELU)
    k_gemm<0><<<dim3(GHD / 128, TT / 128, 1), 512, SMEM>>>(d_xs, d_gw1s, HH, d_act, gb1);
    k_route<<<TT / 8, 256>>>(gw2, gb2, logits);
    k_off_k<<<1, 32>>>();
    // up: int8 fixed-point fused (w1, w3) -> g_hs
    k_upq<<<dim3(FF / 64, TT / 128, NE), 512, SMEM>>>();
    // down: h @ w2^T (bf16 3-product) -> g_y compact
    k_gemm<2><<<dim3(HH / 128, TT / 128, NE), 512, SMEM>>>(d_hs, d_w2s, FF, d_y, nullptr);
    // combine: out[t] = w0*y[r0] + w1*y[r1]
    k_combine<<<(TT * (HH / 4) + 255) / 256, 256>>>(out);
}